// round 4
// baseline (speedup 1.0000x reference)
#include <cuda_runtime.h>
#include <cuda_bf16.h>
#include <cstdint>

#define NN 64
#define CI 256
#define CO 256
#define CR 32
#define TT 64
#define VV 25
#define TV 1600   // T*V
#define UV 625    // V*V
#define NROWS (NN*TV)       // 102400
#define NTILES (NROWS/128)  // 800

// ---------------- scratch ----------------
__device__ float g_xm[NN*CI*VV];
__device__ float g_x1[NN*CR*VV];
__device__ float g_x2[NN*CR*VV];
__device__ float g_attn[NN*CO*UV];                  // (n, co, u*25+v)
__device__ __nv_bfloat16 g_ahi[(size_t)NROWS*CI];   // bf16(x)        [row, c]
__device__ uint8_t g_a1[(size_t)NROWS*CI];          // e4m3(x_lo*2^12)
__device__ uint8_t g_a2[(size_t)NROWS*CI];          // e4m3(x)
__device__ __nv_bfloat16 g_bhi[CO*CI];              // bf16(w3)       [co, c]
__device__ uint8_t g_b1[CO*CI];                     // e4m3(w3*2^4)
__device__ uint8_t g_b2[CO*CI];                     // e4m3(w3_lo*2^16)
__device__ float g_x3[(size_t)NROWS*CO];            // [row=(n,t,u), co]

// ---------------- helpers ----------------
__device__ __forceinline__ uint32_t smem_u32(const void* p) {
    uint32_t a;
    asm("{ .reg .u64 t; cvta.to.shared.u64 t, %1; cvt.u32.u64 %0, t; }" : "=r"(a) : "l"(p));
    return a;
}
__device__ __forceinline__ uint32_t swz(uint32_t o) { return o ^ ((o >> 3) & 0x70); }

#define CPA(dst, src) asm volatile("cp.async.cg.shared.global [%0], [%1], 16;" \
                                   :: "r"(dst), "l"(src) : "memory")
#define CPC() asm volatile("cp.async.commit_group;" ::: "memory")
#define CPW(n) asm volatile("cp.async.wait_group %0;" :: "n"(n) : "memory")

__device__ __forceinline__ void ldsm4(uint32_t& r0, uint32_t& r1, uint32_t& r2, uint32_t& r3,
                                      uint32_t a) {
    asm volatile("ldmatrix.sync.aligned.m8n8.x4.shared.b16 {%0,%1,%2,%3}, [%4];"
                 : "=r"(r0), "=r"(r1), "=r"(r2), "=r"(r3) : "r"(a));
}
__device__ __forceinline__ void mma16816(float* d, const uint32_t* a, const uint32_t* b) {
    asm volatile("mma.sync.aligned.m16n8k16.row.col.f32.bf16.bf16.f32 "
                 "{%0,%1,%2,%3}, {%4,%5,%6,%7}, {%8,%9}, {%0,%1,%2,%3};"
                 : "+f"(d[0]), "+f"(d[1]), "+f"(d[2]), "+f"(d[3])
                 : "r"(a[0]), "r"(a[1]), "r"(a[2]), "r"(a[3]), "r"(b[0]), "r"(b[1]));
}
__device__ __forceinline__ void mma16832q(float* d, const uint32_t* a, const uint32_t* b) {
    asm volatile("mma.sync.aligned.m16n8k32.row.col.f32.e4m3.e4m3.f32 "
                 "{%0,%1,%2,%3}, {%4,%5,%6,%7}, {%8,%9}, {%0,%1,%2,%3};"
                 : "+f"(d[0]), "+f"(d[1]), "+f"(d[2]), "+f"(d[3])
                 : "r"(a[0]), "r"(a[1]), "r"(a[2]), "r"(a[3]), "r"(b[0]), "r"(b[1]));
}
__device__ __forceinline__ unsigned short pk_e4m3(float lo, float hi) {
    unsigned short r;
    asm("cvt.rn.satfinite.e4m3x2.f32 %0, %1, %2;" : "=h"(r) : "f"(hi), "f"(lo));
    return r;
}

// ---------------- K0: transpose + split x, fused T-mean ----------------
// grid (8 cblk, 64 n); each CTA owns (n, 32 channels, all tv)
__global__ __launch_bounds__(256) void k_xcvt(const float* __restrict__ x) {
    __shared__ float tile[32][33];
    __shared__ float sxm[32][26];
    int n = blockIdx.y, c0 = blockIdx.x*32;
    int tid = threadIdx.x;
    for (int i = tid; i < 32*26; i += 256) (&sxm[0][0])[i] = 0.f;
    int tx = tid & 31, ty = tid >> 5;
    int wtx = tid & 15, wty = tid >> 4;
    const float* xb = x + ((size_t)n*CI + c0)*TV;
    for (int j = 0; j < 50; j++) {
        int tv0 = j*32;
        __syncthreads();
        #pragma unroll
        for (int i = 0; i < 4; i++)
            tile[ty + i*8][tx] = xb[(size_t)(ty + i*8)*TV + tv0 + tx];
        __syncthreads();
        #pragma unroll
        for (int p = 0; p < 2; p++) {
            int tvl = wty + p*16;
            float v0 = tile[wtx*2][tvl], v1 = tile[wtx*2+1][tvl];
            __nv_bfloat16 h0 = __float2bfloat16(v0), h1 = __float2bfloat16(v1);
            float l0 = v0 - __bfloat162float(h0), l1 = v1 - __bfloat162float(h1);
            size_t row = (size_t)n*TV + tv0 + tvl;
            __nv_bfloat162 hh; hh.x = h0; hh.y = h1;
            *(__nv_bfloat162*)&g_ahi[row*CI + c0 + wtx*2] = hh;
            *(unsigned short*)&g_a1[row*CI + c0 + wtx*2] = pk_e4m3(l0*4096.f, l1*4096.f);
            *(unsigned short*)&g_a2[row*CI + c0 + wtx*2] = pk_e4m3(v0, v1);
            int v = (tv0 + tvl) % 25;
            atomicAdd(&sxm[wtx*2][v], v0);
            atomicAdd(&sxm[wtx*2+1][v], v1);
        }
    }
    __syncthreads();
    for (int i = tid; i < 800; i += 256)
        g_xm[n*(CI*VV) + c0*VV + i] = sxm[i/25][i%25] * (1.0f/64.0f);
}

// ---------------- K1: w3 split ----------------
__global__ void k_w3cvt(const float* __restrict__ w3) {
    int i = blockIdx.x*256 + threadIdx.x;   // pair index
    float v0 = w3[2*i], v1 = w3[2*i+1];
    __nv_bfloat16 h0 = __float2bfloat16(v0), h1 = __float2bfloat16(v1);
    __nv_bfloat162 hh; hh.x = h0; hh.y = h1;
    *(__nv_bfloat162*)&g_bhi[2*i] = hh;
    *(unsigned short*)&g_b1[2*i] = pk_e4m3(v0*16.f, v1*16.f);
    float l0 = v0 - __bfloat162float(h0), l1 = v1 - __bfloat162float(h1);
    *(unsigned short*)&g_b2[2*i] = pk_e4m3(l0*65536.f, l1*65536.f);
}

// ---------------- K2: x1/x2 ----------------
__global__ void k_x12(const float* __restrict__ w1, const float* __restrict__ b1,
                      const float* __restrict__ w2, const float* __restrict__ b2) {
    __shared__ float xm_s[CI*VV];
    int n = blockIdx.x;
    for (int i = threadIdx.x; i < CI*VV; i += 256) xm_s[i] = g_xm[n*(CI*VV) + i];
    __syncthreads();
    for (int i = threadIdx.x; i < 2*CR*VV; i += 256) {
        int sel = i / (CR*VV);
        int rv  = i - sel*(CR*VV);
        int r = rv / VV, v = rv - r*VV;
        const float* w = sel ? w2 : w1;
        float s = sel ? b2[r] : b1[r];
        #pragma unroll 8
        for (int c = 0; c < CI; c++) s += w[r*CI + c] * xm_s[c*VV + v];
        (sel ? g_x2 : g_x1)[n*(CR*VV) + rv] = s;
    }
}

// ---------------- K3: fused aff+attn: attn = w4@tanh(x1-x2) + b4 + A ----------------
// grid (uvt 10, cot 2, n 64); CTA = 128 co x 64 uv, K=32
__global__ __launch_bounds__(256) void k_attn2(const float* __restrict__ w4,
                                               const float* __restrict__ b4,
                                               const float* __restrict__ A) {
    __shared__ float w4s[32][132];
    __shared__ float affs[32][68];
    __shared__ float x1s[32][25], x2s[32][25];
    int n = blockIdx.z, cot = blockIdx.y, uvt = blockIdx.x;
    int co0 = cot*128, uv0 = uvt*64;
    int tid = threadIdx.x;
    for (int i = tid; i < 800; i += 256) {
        x1s[i/25][i%25] = g_x1[n*800 + i];
        x2s[i/25][i%25] = g_x2[n*800 + i];
    }
    for (int i = tid; i < 4096; i += 256) {
        int co = i >> 5, k = i & 31;
        w4s[k][co] = w4[(co0+co)*32 + k];
    }
    __syncthreads();
    for (int i = tid; i < 2048; i += 256) {
        int r = i >> 6, l = i & 63, uv = uv0 + l;
        float val = 0.f;
        if (uv < 625) {
            int u = uv / 25, v = uv - u*25;
            val = tanhf(x1s[r][u] - x2s[r][v]);
        }
        affs[r][l] = val;
    }
    __syncthreads();
    int txc = tid & 15, txu = tid >> 4;
    float acc[8][4] = {};
    #pragma unroll
    for (int k = 0; k < 32; k++) {
        float4 b = *(const float4*)&affs[k][txu*4];
        float4 a0 = *(const float4*)&w4s[k][txc*8];
        float4 a1 = *(const float4*)&w4s[k][txc*8+4];
        float av[8] = {a0.x,a0.y,a0.z,a0.w,a1.x,a1.y,a1.z,a1.w};
        #pragma unroll
        for (int i = 0; i < 8; i++) {
            acc[i][0] += av[i]*b.x; acc[i][1] += av[i]*b.y;
            acc[i][2] += av[i]*b.z; acc[i][3] += av[i]*b.w;
        }
    }
    #pragma unroll
    for (int i = 0; i < 8; i++) {
        int co = co0 + txc*8 + i;
        float bb = b4[co];
        #pragma unroll
        for (int j = 0; j < 4; j++) {
            int uv = uv0 + txu*4 + j;
            if (uv < 625)
                g_attn[((size_t)n*CO + co)*UV + uv] = acc[i][j] + bb + A[uv];
        }
    }
}

// ---------------- K4: GEMM x3 = x@w3^T + b3 (bf16 hi*hi + fp8 cross terms) ----------------
// smem per stage: ah 16K | bh 16K | a1 10K | a2 10K | b1 10K | b2 10K
#define SO_AH 0
#define SO_BH 16384
#define SO_A1 32768
#define SO_A2 43008
#define SO_B1 53248
#define SO_B2 63488
#define STAGE_BYTES 73728
#define MMA_SMEM (2*STAGE_BYTES)

__global__ __launch_bounds__(256, 1) void k_mma(const float* __restrict__ b3) {
    extern __shared__ __align__(1024) char smem[];
    uint32_t sb = smem_u32(smem);
    int tid = threadIdx.x, lane = tid & 31, wid = tid >> 5;
    int tile = blockIdx.x, co0 = blockIdx.y * 128;

    const __nv_bfloat16* abh = g_ahi + (size_t)tile*128*CI;
    const uint8_t* pa1 = g_a1 + (size_t)tile*128*CI;
    const uint8_t* pa2 = g_a2 + (size_t)tile*128*CI;
    const __nv_bfloat16* bbh = g_bhi + (size_t)co0*CI;
    const uint8_t* pb1 = g_b1 + (size_t)co0*CI;
    const uint8_t* pb2 = g_b2 + (size_t)co0*CI;

    auto load_chunk = [&](int kb, int stage) {
        uint32_t s0 = sb + stage*STAGE_BYTES;
        const uint4* gah = (const uint4*)(abh + kb*64);
        const uint4* gbh = (const uint4*)(bbh + kb*64);
        int q = tid & 7;
        #pragma unroll
        for (int it = 0; it < 4; it++) {
            int r = (tid >> 3) + it*32;
            uint32_t so = swz((uint32_t)(r*128 + q*16));
            CPA(s0 + SO_AH + so, gah + r*32 + q);
            CPA(s0 + SO_BH + so, gbh + r*32 + q);
        }
        const uint4* ga1 = (const uint4*)(pa1 + kb*64);
        const uint4* ga2 = (const uint4*)(pa2 + kb*64);
        const uint4* gb1 = (const uint4*)(pb1 + kb*64);
        const uint4* gb2 = (const uint4*)(pb2 + kb*64);
        int q2 = tid & 3;
        #pragma unroll
        for (int it = 0; it < 2; it++) {
            int r = (tid >> 2) + it*64;
            uint32_t so = (uint32_t)(r*80 + q2*16);
            CPA(s0 + SO_A1 + so, ga1 + r*16 + q2);
            CPA(s0 + SO_A2 + so, ga2 + r*16 + q2);
            CPA(s0 + SO_B1 + so, gb1 + r*16 + q2);
            CPA(s0 + SO_B2 + so, gb2 + r*16 + q2);
        }
        CPC();
    };

    int m0 = (wid & 3) * 32, n0 = (wid >> 2) * 64;
    float acc[2][8][4], accx[2][8][4];
    #pragma unroll
    for (int mt = 0; mt < 2; mt++)
        #pragma unroll
        for (int nt = 0; nt < 8; nt++)
            #pragma unroll
            for (int k = 0; k < 4; k++) { acc[mt][nt][k] = 0.f; accx[mt][nt][k] = 0.f; }

    load_chunk(0, 0);
    load_chunk(1, 1);

    int a_row = lane & 15;
    int a_seg = lane >> 4;
    int b_row = ((lane >> 4) & 1) * 8 + (lane & 7);
    int b_seg = (lane >> 3) & 1;

    #pragma unroll
    for (int kb = 0; kb < 4; kb++) {
        if (kb < 3) { CPW(1); } else { CPW(0); }
        __syncthreads();
        uint32_t s0 = sb + (kb & 1)*STAGE_BYTES;
        // ---- bf16 hi*hi ----
        #pragma unroll
        for (int ks = 0; ks < 4; ks++) {
            uint32_t ah[2][4], bh[16];
            #pragma unroll
            for (int mt = 0; mt < 2; mt++) {
                uint32_t off = swz((uint32_t)((m0 + mt*16 + a_row)*128 + ks*32 + a_seg*16));
                ldsm4(ah[mt][0], ah[mt][1], ah[mt][2], ah[mt][3], s0 + SO_AH + off);
            }
            #pragma unroll
            for (int np = 0; np < 4; np++) {
                uint32_t off = swz((uint32_t)((n0 + np*16 + b_row)*128 + ks*32 + b_seg*16));
                ldsm4(bh[np*4+0], bh[np*4+1], bh[np*4+2], bh[np*4+3], s0 + SO_BH + off);
            }
            #pragma unroll
            for (int mt = 0; mt < 2; mt++)
                #pragma unroll
                for (int nt = 0; nt < 8; nt++)
                    mma16816(acc[mt][nt], ah[mt], &bh[nt*2]);
        }
        // ---- fp8 cross terms ----
        #pragma unroll
        for (int ks2 = 0; ks2 < 2; ks2++) {
            uint32_t f1[2][4], f2[2][4], g1[16], g2[16];
            #pragma unroll
            for (int mt = 0; mt < 2; mt++) {
                uint32_t off = (uint32_t)((m0 + mt*16 + a_row)*80 + ks2*32 + a_seg*16);
                ldsm4(f1[mt][0], f1[mt][1], f1[mt][2], f1[mt][3], s0 + SO_A1 + off);
                ldsm4(f2[mt][0], f2[mt][1], f2[mt][2], f2[mt][3], s0 + SO_A2 + off);
            }
            #pragma unroll
            for (int np = 0; np < 4; np++) {
                uint32_t off = (uint32_t)((n0 + np*16 + b_row)*80 + ks2*32 + b_seg*16);
                ldsm4(g1[np*4+0], g1[np*4+1], g1[np*4+2], g1[np*4+3], s0 + SO_B1 + off);
                ldsm4(g2[np*4+0], g2[np*4+1], g2[np*4+2], g2[np*4+3], s0 + SO_B2 + off);
            }
            #pragma unroll
            for (int mt = 0; mt < 2; mt++)
                #pragma unroll
                for (int nt = 0; nt < 8; nt++) {
                    mma16832q(accx[mt][nt], f1[mt], &g1[nt*2]);   // x_lo*2^12 · w3*2^4
                    mma16832q(accx[mt][nt], f2[mt], &g2[nt*2]);   // x · w3_lo*2^16
                }
        }
        __syncthreads();
        if (kb < 2) load_chunk(kb + 2, kb & 1);
    }

    // -------- store x3 (+b3), fold cross scale 2^-16 --------
    const float CS = 1.0f/65536.0f;
    size_t rowg0 = (size_t)tile * 128;
    #pragma unroll
    for (int mt = 0; mt < 2; mt++) {
        int r0 = m0 + mt*16 + (lane >> 2);
        #pragma unroll
        for (int nt = 0; nt < 8; nt++) {
            int c = co0 + n0 + nt*8 + (lane & 3)*2;
            float2 bb = *(const float2*)(b3 + c);
            float2 v0, v1;
            v0.x = acc[mt][nt][0] + accx[mt][nt][0]*CS + bb.x;
            v0.y = acc[mt][nt][1] + accx[mt][nt][1]*CS + bb.y;
            v1.x = acc[mt][nt][2] + accx[mt][nt][2]*CS + bb.x;
            v1.y = acc[mt][nt][3] + accx[mt][nt][3]*CS + bb.y;
            *(float2*)(g_x3 + (rowg0 + r0    )*CO + c) = v0;
            *(float2*)(g_x3 + (rowg0 + r0 + 8)*CO + c) = v1;
        }
    }
}

// ---------------- K5: out[n,co,t,v] = sum_u attn[n,co,u,v] * x3[n,(t,u),co] ----------------
// CTA = 16 co x 32 t; dynamic smem 96000 B
#define OUT_SMEM ((16*700 + 32*25*16)*4)
__global__ __launch_bounds__(256) void k_out(float* __restrict__ out) {
    extern __shared__ __align__(16) float osm[];
    float* attn_s = osm;            // 16*700
    float* x3_s = osm + 16*700;     // 32*25*16
    int n = blockIdx.y;
    int cot = blockIdx.x >> 1, tt = blockIdx.x & 1;
    int co0 = cot*16, t0 = tt*32;
    int tid = threadIdx.x;

    const float* ab = g_attn + ((size_t)n*CO + co0)*UV;
    for (int i = tid; i < 16*700; i += 256) {
        int co = i / 700, rem = i - co*700;
        int u = rem / 28, v = rem - u*28;
        attn_s[i] = (v < VV) ? ab[co*UV + u*VV + v] : 0.f;
    }
    const float* xb = g_x3 + ((size_t)n*TV + t0*25)*CO + co0;
    for (int i = tid; i < 32*25*16; i += 256) {
        int r = i >> 4, co = i & 15;
        x3_s[i] = xb[(size_t)r*CO + co];
    }
    __syncthreads();

    int co = tid & 15, tl = tid >> 4;
    const float* arow = attn_s + co*700;
    #pragma unroll
    for (int h = 0; h < 2; h++) {
        int t = tl + h*16;
        const float* x3r = x3_s + (t*25)*16 + co;
        float4 o0={0,0,0,0},o1={0,0,0,0},o2={0,0,0,0},o3={0,0,0,0},o4={0,0,0,0},o5={0,0,0,0};
        float o24 = 0.f;
        for (int u = 0; u < 25; u++) {
            float xv = x3r[u*16];
            const float4* av = (const float4*)(arow + u*28);
            float4 a0=av[0],a1=av[1],a2=av[2],a3=av[3],a4=av[4],a5=av[5];
            float  a24 = arow[u*28 + 24];
            o0.x += xv*a0.x; o0.y += xv*a0.y; o0.z += xv*a0.z; o0.w += xv*a0.w;
            o1.x += xv*a1.x; o1.y += xv*a1.y; o1.z += xv*a1.z; o1.w += xv*a1.w;
            o2.x += xv*a2.x; o2.y += xv*a2.y; o2.z += xv*a2.z; o2.w += xv*a2.w;
            o3.x += xv*a3.x; o3.y += xv*a3.y; o3.z += xv*a3.z; o3.w += xv*a3.w;
            o4.x += xv*a4.x; o4.y += xv*a4.y; o4.z += xv*a4.z; o4.w += xv*a4.w;
            o5.x += xv*a5.x; o5.y += xv*a5.y; o5.z += xv*a5.z; o5.w += xv*a5.w;
            o24  += xv*a24;
        }
        float* op = out + (((size_t)(n*CO + co0 + co))*TT + t0 + t)*VV;
        op[0]=o0.x;  op[1]=o0.y;  op[2]=o0.z;  op[3]=o0.w;
        op[4]=o1.x;  op[5]=o1.y;  op[6]=o1.z;  op[7]=o1.w;
        op[8]=o2.x;  op[9]=o2.y;  op[10]=o2.z; op[11]=o2.w;
        op[12]=o3.x; op[13]=o3.y; op[14]=o3.z; op[15]=o3.w;
        op[16]=o4.x; op[17]=o4.y; op[18]=o4.z; op[19]=o4.w;
        op[20]=o5.x; op[21]=o5.y; op[22]=o5.z; op[23]=o5.w;
        op[24]=o24;
    }
}

// ---------------- launch ----------------
extern "C" void kernel_launch(void* const* d_in, const int* in_sizes, int n_in,
                              void* d_out, int out_size) {
    const float* x  = (const float*)d_in[0];
    const float* A  = (const float*)d_in[1];
    const float* w1 = (const float*)d_in[2];
    const float* b1 = (const float*)d_in[3];
    const float* w2 = (const float*)d_in[4];
    const float* b2 = (const float*)d_in[5];
    const float* w3 = (const float*)d_in[6];
    const float* b3 = (const float*)d_in[7];
    const float* w4 = (const float*)d_in[8];
    const float* b4 = (const float*)d_in[9];
    float* out = (float*)d_out;

    cudaFuncSetAttribute(k_mma, cudaFuncAttributeMaxDynamicSharedMemorySize, MMA_SMEM);
    cudaFuncSetAttribute(k_out, cudaFuncAttributeMaxDynamicSharedMemorySize, OUT_SMEM);

    k_xcvt <<<dim3(8, 64), 256>>>(x);
    k_w3cvt<<<128, 256>>>(w3);
    k_x12  <<<64, 256>>>(w1, b1, w2, b2);
    k_attn2<<<dim3(10, 2, 64), 256>>>(w4, b4, A);
    k_mma  <<<dim3(NTILES, 2), 256, MMA_SMEM>>>(b3);
    k_out  <<<dim3(32, 64), 256, OUT_SMEM>>>(out);
}

// round 5
// speedup vs baseline: 1.1651x; 1.1651x over previous
#include <cuda_runtime.h>
#include <cuda_bf16.h>
#include <cstdint>

#define NN 64
#define CI 256
#define CO 256
#define CR 32
#define TT 64
#define VV 25
#define TV 1600   // T*V
#define UV 625    // V*V
#define NROWS (NN*TV)       // 102400
#define NTILES (NROWS/128)  // 800

// ---------------- scratch ----------------
__device__ float g_xm[NN*CI*VV];
__device__ float g_x1[NN*CR*VV];
__device__ float g_x2[NN*CR*VV];
__device__ float g_aff[NN*CR*UV];
__device__ float g_attn[NN*CO*UV];                  // (n, co, u*25+v)
__device__ __nv_bfloat16 g_ahi[(size_t)NROWS*CI];   // bf16(x)        [row, c]
__device__ uint8_t g_a1[(size_t)NROWS*CI];          // e4m3(x_lo*2^12)
__device__ uint8_t g_a2[(size_t)NROWS*CI];          // e4m3(x)
__device__ __nv_bfloat16 g_bhi[CO*CI];              // bf16(w3)       [co, c]
__device__ uint8_t g_b1[CO*CI];                     // e4m3(w3*2^4)
__device__ uint8_t g_b2[CO*CI];                     // e4m3(w3_lo*2^16)
__device__ float g_x3[(size_t)NROWS*CO];            // [row=(n,t,u), co]

// ---------------- helpers ----------------
__device__ __forceinline__ uint32_t smem_u32(const void* p) {
    uint32_t a;
    asm("{ .reg .u64 t; cvta.to.shared.u64 t, %1; cvt.u32.u64 %0, t; }" : "=r"(a) : "l"(p));
    return a;
}
__device__ __forceinline__ uint32_t swz(uint32_t o) { return o ^ ((o >> 3) & 0x70); }

#define CPA(dst, src) asm volatile("cp.async.cg.shared.global [%0], [%1], 16;" \
                                   :: "r"(dst), "l"(src) : "memory")
#define CPC() asm volatile("cp.async.commit_group;" ::: "memory")
#define CPW(n) asm volatile("cp.async.wait_group %0;" :: "n"(n) : "memory")

__device__ __forceinline__ void ldsm4(uint32_t& r0, uint32_t& r1, uint32_t& r2, uint32_t& r3,
                                      uint32_t a) {
    asm volatile("ldmatrix.sync.aligned.m8n8.x4.shared.b16 {%0,%1,%2,%3}, [%4];"
                 : "=r"(r0), "=r"(r1), "=r"(r2), "=r"(r3) : "r"(a));
}
__device__ __forceinline__ void mma16816(float* d, const uint32_t* a, const uint32_t* b) {
    asm volatile("mma.sync.aligned.m16n8k16.row.col.f32.bf16.bf16.f32 "
                 "{%0,%1,%2,%3}, {%4,%5,%6,%7}, {%8,%9}, {%0,%1,%2,%3};"
                 : "+f"(d[0]), "+f"(d[1]), "+f"(d[2]), "+f"(d[3])
                 : "r"(a[0]), "r"(a[1]), "r"(a[2]), "r"(a[3]), "r"(b[0]), "r"(b[1]));
}
__device__ __forceinline__ void mma16832q(float* d, const uint32_t* a, const uint32_t* b) {
    asm volatile("mma.sync.aligned.m16n8k32.row.col.f32.e4m3.e4m3.f32 "
                 "{%0,%1,%2,%3}, {%4,%5,%6,%7}, {%8,%9}, {%0,%1,%2,%3};"
                 : "+f"(d[0]), "+f"(d[1]), "+f"(d[2]), "+f"(d[3])
                 : "r"(a[0]), "r"(a[1]), "r"(a[2]), "r"(a[3]), "r"(b[0]), "r"(b[1]));
}
__device__ __forceinline__ unsigned short pk_e4m3(float lo, float hi) {
    unsigned short r;
    asm("cvt.rn.satfinite.e4m3x2.f32 %0, %1, %2;" : "=h"(r) : "f"(hi), "f"(lo));
    return r;
}

// ---------------- K0: xm = mean_t x ----------------
__global__ void k_xm(const float* __restrict__ x) {
    __shared__ float sx[4*TV];
    int n = blockIdx.y, cc = blockIdx.x;
    const float* xb = x + ((size_t)(n*CI + cc*4))*TV;
    for (int i = threadIdx.x; i < 4*TV; i += 256) sx[i] = xb[i];
    __syncthreads();
    if (threadIdx.x < 100) {
        int c = threadIdx.x / VV, v = threadIdx.x - c*VV;
        float s = 0.f;
        #pragma unroll
        for (int t = 0; t < TT; t++) s += sx[c*TV + t*VV + v];
        g_xm[n*(CI*VV) + cc*100 + threadIdx.x] = s * (1.0f/64.0f);
    }
}

// ---------------- K1: x1/x2 ----------------
__global__ void k_x12(const float* __restrict__ w1, const float* __restrict__ b1,
                      const float* __restrict__ w2, const float* __restrict__ b2) {
    __shared__ float xm_s[CI*VV];
    int n = blockIdx.x;
    for (int i = threadIdx.x; i < CI*VV; i += 256) xm_s[i] = g_xm[n*(CI*VV) + i];
    __syncthreads();
    for (int i = threadIdx.x; i < 2*CR*VV; i += 256) {
        int sel = i / (CR*VV);
        int rv  = i - sel*(CR*VV);
        int r = rv / VV, v = rv - r*VV;
        const float* w = sel ? w2 : w1;
        float s = sel ? b2[r] : b1[r];
        #pragma unroll 8
        for (int c = 0; c < CI; c++) s += w[r*CI + c] * xm_s[c*VV + v];
        (sel ? g_x2 : g_x1)[n*(CR*VV) + rv] = s;
    }
}

// ---------------- K2: aff = tanh(x1[u] - x2[v]) ----------------
__global__ void k_aff() {
    __shared__ float s1[CR*VV], s2[CR*VV];
    int n = blockIdx.x;
    for (int i = threadIdx.x; i < CR*VV; i += 256) {
        s1[i] = g_x1[n*(CR*VV) + i];
        s2[i] = g_x2[n*(CR*VV) + i];
    }
    __syncthreads();
    for (int i = threadIdx.x; i < CR*UV; i += 256) {
        int r = i / UV, uv = i - r*UV;
        int u = uv / VV, v = uv - u*VV;
        g_aff[n*(CR*UV) + i] = tanhf(s1[r*VV + u] - s2[r*VV + v]);
    }
}

// ---------------- K3: attn = w4@aff + b4 + A ----------------
__global__ void k_attn(const float* __restrict__ w4, const float* __restrict__ b4,
                       const float* __restrict__ A) {
    __shared__ __align__(16) float w4s[64*CR];
    __shared__ __align__(16) float affs[CR*64];
    int n = blockIdx.z, cot = blockIdx.y, uvt = blockIdx.x;
    int co0 = cot*64, uv0 = uvt*64;
    int tx = threadIdx.x & 15, ty = threadIdx.x >> 4;

    for (int i = threadIdx.x; i < 64*CR; i += 256) w4s[i] = w4[co0*CR + i];
    for (int i = threadIdx.x; i < CR*64; i += 256) {
        int r = i >> 6, c = i & 63;
        affs[i] = (uv0 + c < UV) ? g_aff[n*(CR*UV) + r*UV + uv0 + c] : 0.f;
    }
    __syncthreads();

    float acc[4][4] = {};
    #pragma unroll
    for (int k = 0; k < CR; k++) {
        float4 b = *(const float4*)&affs[k*64 + tx*4];
        #pragma unroll
        for (int i = 0; i < 4; i++) {
            float a = w4s[(ty*4 + i)*CR + k];
            acc[i][0] += a*b.x; acc[i][1] += a*b.y;
            acc[i][2] += a*b.z; acc[i][3] += a*b.w;
        }
    }
    #pragma unroll
    for (int i = 0; i < 4; i++) {
        int co = co0 + ty*4 + i;
        float bb = b4[co];
        #pragma unroll
        for (int j = 0; j < 4; j++) {
            int uv = uv0 + tx*4 + j;
            if (uv < UV)
                g_attn[((size_t)n*CO + co)*UV + uv] = acc[i][j] + bb + A[uv];
        }
    }
}

// ---------------- K4: w3 split (bf16 hi + two e4m3) ----------------
__global__ void k_w3cvt(const float* __restrict__ w3) {
    int i = blockIdx.x*256 + threadIdx.x;   // pair index
    float v0 = w3[2*i], v1 = w3[2*i+1];
    __nv_bfloat16 h0 = __float2bfloat16(v0), h1 = __float2bfloat16(v1);
    __nv_bfloat162 hh; hh.x = h0; hh.y = h1;
    *(__nv_bfloat162*)&g_bhi[2*i] = hh;
    *(unsigned short*)&g_b1[2*i] = pk_e4m3(v0*16.f, v1*16.f);
    float l0 = v0 - __bfloat162float(h0), l1 = v1 - __bfloat162float(h1);
    *(unsigned short*)&g_b2[2*i] = pk_e4m3(l0*65536.f, l1*65536.f);
}

// ---------------- K5: transpose + split x (R3 grid: 50 x 8 x 64) ----------------
__global__ __launch_bounds__(256) void k_xcvt(const float* __restrict__ x) {
    __shared__ float tile[32][33];
    int n = blockIdx.z, c0 = blockIdx.y*32, tv0 = blockIdx.x*32;
    int tx = threadIdx.x & 31, ty = threadIdx.x >> 5;   // 32 x 8
    #pragma unroll
    for (int i = 0; i < 4; i++) {
        int c = c0 + ty + i*8;
        tile[ty + i*8][tx] = x[((size_t)(n*CI + c))*TV + tv0 + tx];
    }
    __syncthreads();
    int wtx = threadIdx.x & 15, wty = threadIdx.x >> 4;  // 16 c-pairs x 16 tv
    #pragma unroll
    for (int p = 0; p < 2; p++) {
        int tvl = wty + p*16;
        float v0 = tile[wtx*2][tvl], v1 = tile[wtx*2 + 1][tvl];
        __nv_bfloat16 h0 = __float2bfloat16(v0), h1 = __float2bfloat16(v1);
        float l0 = v0 - __bfloat162float(h0), l1 = v1 - __bfloat162float(h1);
        size_t row = (size_t)n*TV + tv0 + tvl;
        __nv_bfloat162 hh; hh.x = h0; hh.y = h1;
        *(__nv_bfloat162*)&g_ahi[row*CI + c0 + wtx*2] = hh;
        *(unsigned short*)&g_a1[row*CI + c0 + wtx*2] = pk_e4m3(l0*4096.f, l1*4096.f);
        *(unsigned short*)&g_a2[row*CI + c0 + wtx*2] = pk_e4m3(v0, v1);
    }
}

// ---------------- K6: GEMM x3 = x@w3^T + b3 (bf16 hi*hi + fp8 cross terms) ----------------
#define SO_AH 0
#define SO_BH 16384
#define SO_A1 32768
#define SO_A2 43008
#define SO_B1 53248
#define SO_B2 63488
#define STAGE_BYTES 73728
#define MMA_SMEM (2*STAGE_BYTES)

__global__ __launch_bounds__(256, 1) void k_mma(const float* __restrict__ b3) {
    extern __shared__ __align__(1024) char smem[];
    uint32_t sb = smem_u32(smem);
    int tid = threadIdx.x, lane = tid & 31, wid = tid >> 5;
    int tile = blockIdx.x, co0 = blockIdx.y * 128;

    const __nv_bfloat16* abh = g_ahi + (size_t)tile*128*CI;
    const uint8_t* pa1 = g_a1 + (size_t)tile*128*CI;
    const uint8_t* pa2 = g_a2 + (size_t)tile*128*CI;
    const __nv_bfloat16* bbh = g_bhi + (size_t)co0*CI;
    const uint8_t* pb1 = g_b1 + (size_t)co0*CI;
    const uint8_t* pb2 = g_b2 + (size_t)co0*CI;

    auto load_chunk = [&](int kb, int stage) {
        uint32_t s0 = sb + stage*STAGE_BYTES;
        const uint4* gah = (const uint4*)(abh + kb*64);
        const uint4* gbh = (const uint4*)(bbh + kb*64);
        int q = tid & 7;
        #pragma unroll
        for (int it = 0; it < 4; it++) {
            int r = (tid >> 3) + it*32;
            uint32_t so = swz((uint32_t)(r*128 + q*16));
            CPA(s0 + SO_AH + so, gah + r*32 + q);
            CPA(s0 + SO_BH + so, gbh + r*32 + q);
        }
        const uint4* ga1 = (const uint4*)(pa1 + kb*64);
        const uint4* ga2 = (const uint4*)(pa2 + kb*64);
        const uint4* gb1 = (const uint4*)(pb1 + kb*64);
        const uint4* gb2 = (const uint4*)(pb2 + kb*64);
        int q2 = tid & 3;
        #pragma unroll
        for (int it = 0; it < 2; it++) {
            int r = (tid >> 2) + it*64;
            uint32_t so = (uint32_t)(r*80 + q2*16);
            CPA(s0 + SO_A1 + so, ga1 + r*16 + q2);
            CPA(s0 + SO_A2 + so, ga2 + r*16 + q2);
            CPA(s0 + SO_B1 + so, gb1 + r*16 + q2);
            CPA(s0 + SO_B2 + so, gb2 + r*16 + q2);
        }
        CPC();
    };

    int m0 = (wid & 3) * 32, n0 = (wid >> 2) * 64;
    float acc[2][8][4], accx[2][8][4];
    #pragma unroll
    for (int mt = 0; mt < 2; mt++)
        #pragma unroll
        for (int nt = 0; nt < 8; nt++)
            #pragma unroll
            for (int k = 0; k < 4; k++) { acc[mt][nt][k] = 0.f; accx[mt][nt][k] = 0.f; }

    load_chunk(0, 0);
    load_chunk(1, 1);

    int a_row = lane & 15;
    int a_seg = lane >> 4;
    int b_row = ((lane >> 4) & 1) * 8 + (lane & 7);
    int b_seg = (lane >> 3) & 1;

    #pragma unroll
    for (int kb = 0; kb < 4; kb++) {
        if (kb < 3) { CPW(1); } else { CPW(0); }
        __syncthreads();
        uint32_t s0 = sb + (kb & 1)*STAGE_BYTES;
        // ---- bf16 hi*hi ----
        #pragma unroll
        for (int ks = 0; ks < 4; ks++) {
            uint32_t ah[2][4], bh[16];
            #pragma unroll
            for (int mt = 0; mt < 2; mt++) {
                uint32_t off = swz((uint32_t)((m0 + mt*16 + a_row)*128 + ks*32 + a_seg*16));
                ldsm4(ah[mt][0], ah[mt][1], ah[mt][2], ah[mt][3], s0 + SO_AH + off);
            }
            #pragma unroll
            for (int np = 0; np < 4; np++) {
                uint32_t off = swz((uint32_t)((n0 + np*16 + b_row)*128 + ks*32 + b_seg*16));
                ldsm4(bh[np*4+0], bh[np*4+1], bh[np*4+2], bh[np*4+3], s0 + SO_BH + off);
            }
            #pragma unroll
            for (int mt = 0; mt < 2; mt++)
                #pragma unroll
                for (int nt = 0; nt < 8; nt++)
                    mma16816(acc[mt][nt], ah[mt], &bh[nt*2]);
        }
        // ---- fp8 cross terms ----
        #pragma unroll
        for (int ks2 = 0; ks2 < 2; ks2++) {
            uint32_t f1[2][4], f2[2][4], g1[16], g2[16];
            #pragma unroll
            for (int mt = 0; mt < 2; mt++) {
                uint32_t off = (uint32_t)((m0 + mt*16 + a_row)*80 + ks2*32 + a_seg*16);
                ldsm4(f1[mt][0], f1[mt][1], f1[mt][2], f1[mt][3], s0 + SO_A1 + off);
                ldsm4(f2[mt][0], f2[mt][1], f2[mt][2], f2[mt][3], s0 + SO_A2 + off);
            }
            #pragma unroll
            for (int np = 0; np < 4; np++) {
                uint32_t off = (uint32_t)((n0 + np*16 + b_row)*80 + ks2*32 + b_seg*16);
                ldsm4(g1[np*4+0], g1[np*4+1], g1[np*4+2], g1[np*4+3], s0 + SO_B1 + off);
                ldsm4(g2[np*4+0], g2[np*4+1], g2[np*4+2], g2[np*4+3], s0 + SO_B2 + off);
            }
            #pragma unroll
            for (int mt = 0; mt < 2; mt++)
                #pragma unroll
                for (int nt = 0; nt < 8; nt++) {
                    mma16832q(accx[mt][nt], f1[mt], &g1[nt*2]);   // x_lo*2^12 · w3*2^4
                    mma16832q(accx[mt][nt], f2[mt], &g2[nt*2]);   // x · w3_lo*2^16
                }
        }
        __syncthreads();
        if (kb < 2) load_chunk(kb + 2, kb & 1);
    }

    const float CS = 1.0f/65536.0f;
    size_t rowg0 = (size_t)tile * 128;
    #pragma unroll
    for (int mt = 0; mt < 2; mt++) {
        int r0 = m0 + mt*16 + (lane >> 2);
        #pragma unroll
        for (int nt = 0; nt < 8; nt++) {
            int c = co0 + n0 + nt*8 + (lane & 3)*2;
            float2 bb = *(const float2*)(b3 + c);
            float2 v0, v1;
            v0.x = acc[mt][nt][0] + accx[mt][nt][0]*CS + bb.x;
            v0.y = acc[mt][nt][1] + accx[mt][nt][1]*CS + bb.y;
            v1.x = acc[mt][nt][2] + accx[mt][nt][2]*CS + bb.x;
            v1.y = acc[mt][nt][3] + accx[mt][nt][3]*CS + bb.y;
            *(float2*)(g_x3 + (rowg0 + r0    )*CO + c) = v0;
            *(float2*)(g_x3 + (rowg0 + r0 + 8)*CO + c) = v1;
        }
    }
}

// ---------------- K7: out[n,co,t,v] = sum_u attn[n,co,u,v] * x3[n,(t,u),co] ----------------
__global__ __launch_bounds__(256) void k_out(float* __restrict__ out) {
    __shared__ __align__(16) float attn_s[8*700];   // 8 co x 25 u x 28(pad v)
    __shared__ __align__(16) float x3_s[32*25*8];   // [t][u][co]
    int n = blockIdx.y;
    int cot = blockIdx.x >> 1, tt = blockIdx.x & 1;
    int co0 = cot*8, t0 = tt*32;
    int tid = threadIdx.x;

    {
        const float* ab = g_attn + ((size_t)n*CO + co0)*UV;
        for (int i = tid; i < 8*700; i += 256) {
            int co = i / 700, rem = i - co*700;
            int u = rem / 28, v = rem - u*28;
            attn_s[i] = (v < VV) ? ab[co*UV + u*VV + v] : 0.f;
        }
        const float* xb = g_x3 + ((size_t)n*TV + t0*VV)*CO + co0;
        for (int i = tid; i < 32*25*8; i += 256) {
            int r = i >> 3, co = i & 7;      // r = t*25+u
            x3_s[i] = xb[(size_t)r*CO + co];
        }
    }
    __syncthreads();

    int co = tid & 7, tl = tid >> 3;
    const float* arow = attn_s + co*700;
    const float* x3r  = x3_s + tl*200 + co;
    float4 o0={0,0,0,0},o1={0,0,0,0},o2={0,0,0,0},o3={0,0,0,0},o4={0,0,0,0},o5={0,0,0,0};
    float o24 = 0.f;
    for (int u = 0; u < 25; u++) {
        float xv = x3r[u*8];
        const float4* av = (const float4*)(arow + u*28);
        float4 a0=av[0],a1=av[1],a2=av[2],a3=av[3],a4=av[4],a5=av[5];
        float  a24 = arow[u*28 + 24];
        o0.x += xv*a0.x; o0.y += xv*a0.y; o0.z += xv*a0.z; o0.w += xv*a0.w;
        o1.x += xv*a1.x; o1.y += xv*a1.y; o1.z += xv*a1.z; o1.w += xv*a1.w;
        o2.x += xv*a2.x; o2.y += xv*a2.y; o2.z += xv*a2.z; o2.w += xv*a2.w;
        o3.x += xv*a3.x; o3.y += xv*a3.y; o3.z += xv*a3.z; o3.w += xv*a3.w;
        o4.x += xv*a4.x; o4.y += xv*a4.y; o4.z += xv*a4.z; o4.w += xv*a4.w;
        o5.x += xv*a5.x; o5.y += xv*a5.y; o5.z += xv*a5.z; o5.w += xv*a5.w;
        o24  += xv*a24;
    }
    float* op = out + (((size_t)(n*CO + co0 + co))*TT + t0 + tl)*VV;
    op[0]=o0.x;  op[1]=o0.y;  op[2]=o0.z;  op[3]=o0.w;
    op[4]=o1.x;  op[5]=o1.y;  op[6]=o1.z;  op[7]=o1.w;
    op[8]=o2.x;  op[9]=o2.y;  op[10]=o2.z; op[11]=o2.w;
    op[12]=o3.x; op[13]=o3.y; op[14]=o3.z; op[15]=o3.w;
    op[16]=o4.x; op[17]=o4.y; op[18]=o4.z; op[19]=o4.w;
    op[20]=o5.x; op[21]=o5.y; op[22]=o5.z; op[23]=o5.w;
    op[24]=o24;
}

// ---------------- launch ----------------
extern "C" void kernel_launch(void* const* d_in, const int* in_sizes, int n_in,
                              void* d_out, int out_size) {
    const float* x  = (const float*)d_in[0];
    const float* A  = (const float*)d_in[1];
    const float* w1 = (const float*)d_in[2];
    const float* b1 = (const float*)d_in[3];
    const float* w2 = (const float*)d_in[4];
    const float* b2 = (const float*)d_in[5];
    const float* w3 = (const float*)d_in[6];
    const float* b3 = (const float*)d_in[7];
    const float* w4 = (const float*)d_in[8];
    const float* b4 = (const float*)d_in[9];
    float* out = (float*)d_out;

    cudaFuncSetAttribute(k_mma, cudaFuncAttributeMaxDynamicSharedMemorySize, MMA_SMEM);

    k_xm   <<<dim3(64, 64), 256>>>(x);
    k_x12  <<<64, 256>>>(w1, b1, w2, b2);
    k_aff  <<<64, 256>>>();
    k_attn <<<dim3(10, 4, 64), 256>>>(w4, b4, A);
    k_w3cvt<<<128, 256>>>(w3);
    k_xcvt <<<dim3(50, 8, 64), 256>>>(x);
    k_mma  <<<dim3(NTILES, 2), 256, MMA_SMEM>>>(b3);
    k_out  <<<dim3(64, 64), 256>>>(out);
}

// round 6
// speedup vs baseline: 1.3046x; 1.1197x over previous
#include <cuda_runtime.h>
#include <cuda_bf16.h>
#include <cstdint>

#define NN 64
#define CI 256
#define CO 256
#define CR 32
#define TT 64
#define VV 25
#define TV 1600   // T*V
#define UV 625    // V*V
#define NROWS (NN*TV)       // 102400
#define NTILES (NROWS/128)  // 800

// ---------------- scratch ----------------
__device__ float g_xm[NN*CI*VV];
__device__ float g_x1[NN*CR*VV];
__device__ float g_x2[NN*CR*VV];
__device__ float g_attn[NN*CO*UV];                  // (n, co, u*25+v)
__device__ __nv_bfloat16 g_ahi[(size_t)NROWS*CI];   // bf16(x)     [row, c]
__device__ __nv_bfloat16 g_alo[(size_t)NROWS*CI];   // bf16(x - hi)
__device__ __nv_bfloat16 g_bhi[CO*CI];              // bf16(w3)    [co, c]
__device__ __nv_bfloat16 g_blo[CO*CI];
__device__ float g_x3[(size_t)NROWS*CO];            // [row=(n,t,u), co]

// ---------------- helpers ----------------
__device__ __forceinline__ uint32_t smem_u32(const void* p) {
    uint32_t a;
    asm("{ .reg .u64 t; cvta.to.shared.u64 t, %1; cvt.u32.u64 %0, t; }" : "=r"(a) : "l"(p));
    return a;
}
__device__ __forceinline__ uint32_t swz(uint32_t o) { return o ^ ((o >> 3) & 0x70); }

#define CPA(dst, src) asm volatile("cp.async.cg.shared.global [%0], [%1], 16;" \
                                   :: "r"(dst), "l"(src) : "memory")
#define CPC() asm volatile("cp.async.commit_group;" ::: "memory")
#define CPW(n) asm volatile("cp.async.wait_group %0;" :: "n"(n) : "memory")

__device__ __forceinline__ void ldsm4(uint32_t& r0, uint32_t& r1, uint32_t& r2, uint32_t& r3,
                                      uint32_t a) {
    asm volatile("ldmatrix.sync.aligned.m8n8.x4.shared.b16 {%0,%1,%2,%3}, [%4];"
                 : "=r"(r0), "=r"(r1), "=r"(r2), "=r"(r3) : "r"(a));
}
__device__ __forceinline__ void mma16816(float* d, const uint32_t* a, const uint32_t* b) {
    asm volatile("mma.sync.aligned.m16n8k16.row.col.f32.bf16.bf16.f32 "
                 "{%0,%1,%2,%3}, {%4,%5,%6,%7}, {%8,%9}, {%0,%1,%2,%3};"
                 : "+f"(d[0]), "+f"(d[1]), "+f"(d[2]), "+f"(d[3])
                 : "r"(a[0]), "r"(a[1]), "r"(a[2]), "r"(a[3]), "r"(b[0]), "r"(b[1]));
}

// ---------------- K0: xm = mean_t x ----------------
__global__ void k_xm(const float* __restrict__ x) {
    __shared__ float sx[4*TV];
    int n = blockIdx.y, cc = blockIdx.x;
    const float* xb = x + ((size_t)(n*CI + cc*4))*TV;
    for (int i = threadIdx.x; i < 4*TV; i += 256) sx[i] = xb[i];
    __syncthreads();
    if (threadIdx.x < 100) {
        int c = threadIdx.x / VV, v = threadIdx.x - c*VV;
        float s = 0.f;
        #pragma unroll
        for (int t = 0; t < TT; t++) s += sx[c*TV + t*VV + v];
        g_xm[n*(CI*VV) + cc*100 + threadIdx.x] = s * (1.0f/64.0f);
    }
}

// ---------------- K1: x1/x2 ----------------
__global__ void k_x12(const float* __restrict__ w1, const float* __restrict__ b1,
                      const float* __restrict__ w2, const float* __restrict__ b2) {
    __shared__ float xm_s[CI*VV];
    int n = blockIdx.x;
    for (int i = threadIdx.x; i < CI*VV; i += 256) xm_s[i] = g_xm[n*(CI*VV) + i];
    __syncthreads();
    for (int i = threadIdx.x; i < 2*CR*VV; i += 256) {
        int sel = i / (CR*VV);
        int rv  = i - sel*(CR*VV);
        int r = rv / VV, v = rv - r*VV;
        const float* w = sel ? w2 : w1;
        float s = sel ? b2[r] : b1[r];
        #pragma unroll 8
        for (int c = 0; c < CI; c++) s += w[r*CI + c] * xm_s[c*VV + v];
        (sel ? g_x2 : g_x1)[n*(CR*VV) + rv] = s;
    }
}

// ---------------- K2: fused attn = w4@tanh(x1-x2) + b4 + A ----------------
// grid (uvt 5, cot 2, n 64); CTA tile 128co x 128uv, K=32, 8x8 per thread
__global__ __launch_bounds__(256) void k_attn2(const float* __restrict__ w4,
                                               const float* __restrict__ b4,
                                               const float* __restrict__ A) {
    __shared__ __align__(16) float w4s[32][132];   // [k][co_local]
    __shared__ __align__(16) float affs[32][132];  // [k][uv_local]
    __shared__ float x1s[CR*VV], x2s[CR*VV];
    __shared__ float sA[128];
    int n = blockIdx.z, cot = blockIdx.y, uvt = blockIdx.x;
    int co0 = cot*128, uv0 = uvt*128;
    int tid = threadIdx.x;

    for (int i = tid; i < CR*VV; i += 256) {
        x1s[i] = g_x1[n*(CR*VV) + i];
        x2s[i] = g_x2[n*(CR*VV) + i];
    }
    for (int i = tid; i < 4096; i += 256) {
        int co = i >> 5, k = i & 31;
        w4s[k][co] = w4[(co0 + co)*CR + k];
    }
    if (tid < 128) {
        int uv = uv0 + tid;
        sA[tid] = (uv < UV) ? A[uv] : 0.f;
    }
    __syncthreads();
    for (int i = tid; i < 4096; i += 256) {
        int k = i >> 7, l = i & 127, uv = uv0 + l;
        float val = 0.f;
        if (uv < UV) {
            int u = uv / VV, v = uv - u*VV;
            val = tanhf(x1s[k*VV + u] - x2s[k*VV + v]);
        }
        affs[k][l] = val;
    }
    __syncthreads();

    int txc = tid & 15, txu = tid >> 4;
    float acc[8][8];
    #pragma unroll
    for (int i = 0; i < 8; i++)
        #pragma unroll
        for (int j = 0; j < 8; j++) acc[i][j] = 0.f;

    #pragma unroll 4
    for (int k = 0; k < CR; k++) {
        float4 a0 = *(const float4*)&w4s[k][txc*8];
        float4 a1 = *(const float4*)&w4s[k][txc*8 + 4];
        float4 b0 = *(const float4*)&affs[k][txu*8];
        float4 b1 = *(const float4*)&affs[k][txu*8 + 4];
        float av[8] = {a0.x,a0.y,a0.z,a0.w,a1.x,a1.y,a1.z,a1.w};
        float bv[8] = {b0.x,b0.y,b0.z,b0.w,b1.x,b1.y,b1.z,b1.w};
        #pragma unroll
        for (int i = 0; i < 8; i++)
            #pragma unroll
            for (int j = 0; j < 8; j++)
                acc[i][j] += av[i]*bv[j];
    }

    #pragma unroll
    for (int i = 0; i < 8; i++) {
        int co = co0 + txc*8 + i;
        float bb = b4[co];
        float* orow = g_attn + ((size_t)n*CO + co)*UV + uv0;
        #pragma unroll
        for (int j = 0; j < 8; j++) {
            int l = txu*8 + j;
            if (uv0 + l < UV)
                orow[l] = acc[i][j] + bb + sA[l];
        }
    }
}

// ---------------- K3: w3 split ----------------
__global__ void k_w3cvt(const float* __restrict__ w3) {
    int i = blockIdx.x*1024 + threadIdx.x;
    float v = w3[i];
    __nv_bfloat16 hi = __float2bfloat16(v);
    g_bhi[i] = hi;
    g_blo[i] = __float2bfloat16(v - __bfloat162float(hi));
}

// ---------------- K4: transpose + split x (50 x 8 x 64) ----------------
__global__ __launch_bounds__(256) void k_xcvt(const float* __restrict__ x) {
    __shared__ float tile[32][33];
    int n = blockIdx.z, c0 = blockIdx.y*32, tv0 = blockIdx.x*32;
    int tx = threadIdx.x & 31, ty = threadIdx.x >> 5;
    #pragma unroll
    for (int i = 0; i < 4; i++) {
        int c = c0 + ty + i*8;
        tile[ty + i*8][tx] = x[((size_t)(n*CI + c))*TV + tv0 + tx];
    }
    __syncthreads();
    int wtx = threadIdx.x & 15, wty = threadIdx.x >> 4;
    #pragma unroll
    for (int p = 0; p < 2; p++) {
        int tvl = wty + p*16;
        float v0 = tile[wtx*2][tvl], v1 = tile[wtx*2 + 1][tvl];
        __nv_bfloat16 h0 = __float2bfloat16(v0), h1 = __float2bfloat16(v1);
        __nv_bfloat162 hh; hh.x = h0; hh.y = h1;
        __nv_bfloat162 ll;
        ll.x = __float2bfloat16(v0 - __bfloat162float(h0));
        ll.y = __float2bfloat16(v1 - __bfloat162float(h1));
        size_t row = (size_t)n*TV + tv0 + tvl;
        *(__nv_bfloat162*)&g_ahi[row*CI + c0 + wtx*2] = hh;
        *(__nv_bfloat162*)&g_alo[row*CI + c0 + wtx*2] = ll;
    }
}

// ---------------- K5: HMMA GEMM x3 = x @ w3^T + b3 (bf16 3-split, fp32 acc) ----------------
#define STAGE_BYTES 65536          // Ahi 16K | Alo 16K | Bhi 16K | Blo 16K
#define MMA_SMEM (2*STAGE_BYTES)

__global__ __launch_bounds__(256, 1) void k_mma(const float* __restrict__ b3) {
    extern __shared__ __align__(1024) char smem[];
    uint32_t sb = smem_u32(smem);
    int tid = threadIdx.x, lane = tid & 31, wid = tid >> 5;
    int tile = blockIdx.x, co0 = blockIdx.y * 128;

    const __nv_bfloat16* abh = g_ahi + (size_t)tile*128*CI;
    const __nv_bfloat16* abl = g_alo + (size_t)tile*128*CI;
    const __nv_bfloat16* bbh = g_bhi + (size_t)co0*CI;
    const __nv_bfloat16* bbl = g_blo + (size_t)co0*CI;

    auto load_chunk = [&](int kb, int stage) {
        uint32_t s0 = sb + stage*STAGE_BYTES;
        const uint4* gah = (const uint4*)(abh + kb*64);
        const uint4* gal = (const uint4*)(abl + kb*64);
        const uint4* gbh = (const uint4*)(bbh + kb*64);
        const uint4* gbl = (const uint4*)(bbl + kb*64);
        int q = tid & 7;
        #pragma unroll
        for (int it = 0; it < 4; it++) {
            int r = (tid >> 3) + it*32;
            uint32_t so = swz((uint32_t)(r*128 + q*16));
            int gi = r*32 + q;
            CPA(s0 +         so, gah + gi);
            CPA(s0 + 16384 + so, gal + gi);
            CPA(s0 + 32768 + so, gbh + gi);
            CPA(s0 + 49152 + so, gbl + gi);
        }
        CPC();
    };

    int m0 = (wid & 3) * 32, n0 = (wid >> 2) * 64;
    float acc[2][8][4];
    #pragma unroll
    for (int mt = 0; mt < 2; mt++)
        #pragma unroll
        for (int nt = 0; nt < 8; nt++)
            #pragma unroll
            for (int k = 0; k < 4; k++) acc[mt][nt][k] = 0.f;

    load_chunk(0, 0);
    load_chunk(1, 1);

    int a_row = lane & 15;
    int a_seg = lane >> 4;
    int b_row = ((lane >> 4) & 1) * 8 + (lane & 7);
    int b_seg = (lane >> 3) & 1;

    #pragma unroll
    for (int kb = 0; kb < 4; kb++) {
        if (kb < 3) { CPW(1); } else { CPW(0); }
        __syncthreads();
        uint32_t s0 = sb + (kb & 1)*STAGE_BYTES;
        #pragma unroll
        for (int ks = 0; ks < 4; ks++) {
            uint32_t ah[2][4], al[2][4], bh[16], bl[16];
            #pragma unroll
            for (int mt = 0; mt < 2; mt++) {
                uint32_t off = swz((uint32_t)((m0 + mt*16 + a_row)*128 + ks*32 + a_seg*16));
                ldsm4(ah[mt][0], ah[mt][1], ah[mt][2], ah[mt][3], s0 + off);
                ldsm4(al[mt][0], al[mt][1], al[mt][2], al[mt][3], s0 + 16384 + off);
            }
            #pragma unroll
            for (int np = 0; np < 4; np++) {
                uint32_t off = swz((uint32_t)((n0 + np*16 + b_row)*128 + ks*32 + b_seg*16));
                ldsm4(bh[np*4+0], bh[np*4+1], bh[np*4+2], bh[np*4+3], s0 + 32768 + off);
                ldsm4(bl[np*4+0], bl[np*4+1], bl[np*4+2], bl[np*4+3], s0 + 49152 + off);
            }
            #pragma unroll
            for (int mt = 0; mt < 2; mt++)
                #pragma unroll
                for (int nt = 0; nt < 8; nt++) {
                    mma16816(acc[mt][nt], ah[mt], &bh[nt*2]);
                    mma16816(acc[mt][nt], ah[mt], &bl[nt*2]);
                    mma16816(acc[mt][nt], al[mt], &bh[nt*2]);
                }
        }
        __syncthreads();
        if (kb < 2) load_chunk(kb + 2, kb & 1);
    }

    size_t rowg0 = (size_t)tile * 128;
    #pragma unroll
    for (int mt = 0; mt < 2; mt++) {
        int r0 = m0 + mt*16 + (lane >> 2);
        #pragma unroll
        for (int nt = 0; nt < 8; nt++) {
            int c = co0 + n0 + nt*8 + (lane & 3)*2;
            float2 bb = *(const float2*)(b3 + c);
            float2 v0, v1;
            v0.x = acc[mt][nt][0] + bb.x;  v0.y = acc[mt][nt][1] + bb.y;
            v1.x = acc[mt][nt][2] + bb.x;  v1.y = acc[mt][nt][3] + bb.y;
            *(float2*)(g_x3 + (rowg0 + r0    )*CO + c) = v0;
            *(float2*)(g_x3 + (rowg0 + r0 + 8)*CO + c) = v1;
        }
    }
}

// ---------------- K6: out[n,co,t,v] = sum_u attn[n,co,u,v] * x3[n,(t,u),co] ----------------
__global__ __launch_bounds__(256) void k_out(float* __restrict__ out) {
    __shared__ __align__(16) float attn_s[8*700];
    __shared__ __align__(16) float x3_s[32*25*8];
    int n = blockIdx.y;
    int cot = blockIdx.x >> 1, tt = blockIdx.x & 1;
    int co0 = cot*8, t0 = tt*32;
    int tid = threadIdx.x;

    {
        const float* ab = g_attn + ((size_t)n*CO + co0)*UV;
        for (int i = tid; i < 8*700; i += 256) {
            int co = i / 700, rem = i - co*700;
            int u = rem / 28, v = rem - u*28;
            attn_s[i] = (v < VV) ? ab[co*UV + u*VV + v] : 0.f;
        }
        const float* xb = g_x3 + ((size_t)n*TV + t0*VV)*CO + co0;
        for (int i = tid; i < 32*25*8; i += 256) {
            int r = i >> 3, co = i & 7;
            x3_s[i] = xb[(size_t)r*CO + co];
        }
    }
    __syncthreads();

    int co = tid & 7, tl = tid >> 3;
    const float* arow = attn_s + co*700;
    const float* x3r  = x3_s + tl*200 + co;
    float4 o0={0,0,0,0},o1={0,0,0,0},o2={0,0,0,0},o3={0,0,0,0},o4={0,0,0,0},o5={0,0,0,0};
    float o24 = 0.f;
    for (int u = 0; u < 25; u++) {
        float xv = x3r[u*8];
        const float4* av = (const float4*)(arow + u*28);
        float4 a0=av[0],a1=av[1],a2=av[2],a3=av[3],a4=av[4],a5=av[5];
        float  a24 = arow[u*28 + 24];
        o0.x += xv*a0.x; o0.y += xv*a0.y; o0.z += xv*a0.z; o0.w += xv*a0.w;
        o1.x += xv*a1.x; o1.y += xv*a1.y; o1.z += xv*a1.z; o1.w += xv*a1.w;
        o2.x += xv*a2.x; o2.y += xv*a2.y; o2.z += xv*a2.z; o2.w += xv*a2.w;
        o3.x += xv*a3.x; o3.y += xv*a3.y; o3.z += xv*a3.z; o3.w += xv*a3.w;
        o4.x += xv*a4.x; o4.y += xv*a4.y; o4.z += xv*a4.z; o4.w += xv*a4.w;
        o5.x += xv*a5.x; o5.y += xv*a5.y; o5.z += xv*a5.z; o5.w += xv*a5.w;
        o24  += xv*a24;
    }
    float* op = out + (((size_t)(n*CO + co0 + co))*TT + t0 + tl)*VV;
    op[0]=o0.x;  op[1]=o0.y;  op[2]=o0.z;  op[3]=o0.w;
    op[4]=o1.x;  op[5]=o1.y;  op[6]=o1.z;  op[7]=o1.w;
    op[8]=o2.x;  op[9]=o2.y;  op[10]=o2.z; op[11]=o2.w;
    op[12]=o3.x; op[13]=o3.y; op[14]=o3.z; op[15]=o3.w;
    op[16]=o4.x; op[17]=o4.y; op[18]=o4.z; op[19]=o4.w;
    op[20]=o5.x; op[21]=o5.y; op[22]=o5.z; op[23]=o5.w;
    op[24]=o24;
}

// ---------------- launch ----------------
extern "C" void kernel_launch(void* const* d_in, const int* in_sizes, int n_in,
                              void* d_out, int out_size) {
    const float* x  = (const float*)d_in[0];
    const float* A  = (const float*)d_in[1];
    const float* w1 = (const float*)d_in[2];
    const float* b1 = (const float*)d_in[3];
    const float* w2 = (const float*)d_in[4];
    const float* b2 = (const float*)d_in[5];
    const float* w3 = (const float*)d_in[6];
    const float* b3 = (const float*)d_in[7];
    const float* w4 = (const float*)d_in[8];
    const float* b4 = (const float*)d_in[9];
    float* out = (float*)d_out;

    cudaFuncSetAttribute(k_mma, cudaFuncAttributeMaxDynamicSharedMemorySize, MMA_SMEM);

    k_xm   <<<dim3(64, 64), 256>>>(x);
    k_x12  <<<64, 256>>>(w1, b1, w2, b2);
    k_attn2<<<dim3(5, 2, 64), 256>>>(w4, b4, A);
    k_w3cvt<<<64, 1024>>>(w3);
    k_xcvt <<<dim3(50, 8, 64), 256>>>(x);
    k_mma  <<<dim3(NTILES, 2), 256, MMA_SMEM>>>(b3);
    k_out  <<<dim3(64, 64), 256>>>(out);
}

// round 7
// speedup vs baseline: 1.3576x; 1.0407x over previous
#include <cuda_runtime.h>
#include <cuda_bf16.h>
#include <cstdint>

#define NN 64
#define CI 256
#define CO 256
#define CR 32
#define TT 64
#define VV 25
#define TV 1600   // T*V
#define UV 625    // V*V
#define NROWS (NN*TV)       // 102400
#define NTILES (NROWS/128)  // 800

// ---------------- scratch ----------------
__device__ float g_xm[NN*CI*VV];
__device__ float g_x1[NN*CR*VV];
__device__ float g_x2[NN*CR*VV];
__device__ float g_aff[NN*CR*UV];
__device__ float g_attn[NN*CO*UV];                  // (n, co, u*25+v)
__device__ __nv_bfloat16 g_ahi[(size_t)NROWS*CI];   // bf16(x)     [row, c]
__device__ __nv_bfloat16 g_alo[(size_t)NROWS*CI];   // bf16(x - hi)
__device__ __nv_bfloat16 g_bhi[CO*CI];              // bf16(w3)    [co, c]
__device__ __nv_bfloat16 g_blo[CO*CI];
__device__ float g_x3[(size_t)NROWS*CO];            // [row=(n,t,u), co]

// ---------------- helpers ----------------
__device__ __forceinline__ uint32_t smem_u32(const void* p) {
    uint32_t a;
    asm("{ .reg .u64 t; cvta.to.shared.u64 t, %1; cvt.u32.u64 %0, t; }" : "=r"(a) : "l"(p));
    return a;
}
__device__ __forceinline__ uint32_t swz(uint32_t o) { return o ^ ((o >> 3) & 0x70); }

#define CPA(dst, src) asm volatile("cp.async.cg.shared.global [%0], [%1], 16;" \
                                   :: "r"(dst), "l"(src) : "memory")
#define CPC() asm volatile("cp.async.commit_group;" ::: "memory")
#define CPW(n) asm volatile("cp.async.wait_group %0;" :: "n"(n) : "memory")

__device__ __forceinline__ void ldsm4(uint32_t& r0, uint32_t& r1, uint32_t& r2, uint32_t& r3,
                                      uint32_t a) {
    asm volatile("ldmatrix.sync.aligned.m8n8.x4.shared.b16 {%0,%1,%2,%3}, [%4];"
                 : "=r"(r0), "=r"(r1), "=r"(r2), "=r"(r3) : "r"(a));
}
__device__ __forceinline__ void mma16816(float* d, const uint32_t* a, const uint32_t* b) {
    asm volatile("mma.sync.aligned.m16n8k16.row.col.f32.bf16.bf16.f32 "
                 "{%0,%1,%2,%3}, {%4,%5,%6,%7}, {%8,%9}, {%0,%1,%2,%3};"
                 : "+f"(d[0]), "+f"(d[1]), "+f"(d[2]), "+f"(d[3])
                 : "r"(a[0]), "r"(a[1]), "r"(a[2]), "r"(a[3]), "r"(b[0]), "r"(b[1]));
}

// ---------------- K: xm = mean_t x ----------------
__global__ void k_xm(const float* __restrict__ x) {
    __shared__ float sx[4*TV];
    int n = blockIdx.y, cc = blockIdx.x;
    const float* xb = x + ((size_t)(n*CI + cc*4))*TV;
    for (int i = threadIdx.x; i < 4*TV; i += 256) sx[i] = xb[i];
    __syncthreads();
    if (threadIdx.x < 100) {
        int c = threadIdx.x / VV, v = threadIdx.x - c*VV;
        float s = 0.f;
        #pragma unroll
        for (int t = 0; t < TT; t++) s += sx[c*TV + t*VV + v];
        g_xm[n*(CI*VV) + cc*100 + threadIdx.x] = s * (1.0f/64.0f);
    }
}

// ---------------- K: x1/x2 ----------------
__global__ void k_x12(const float* __restrict__ w1, const float* __restrict__ b1,
                      const float* __restrict__ w2, const float* __restrict__ b2) {
    __shared__ float xm_s[CI*VV];
    int n = blockIdx.x;
    for (int i = threadIdx.x; i < CI*VV; i += 256) xm_s[i] = g_xm[n*(CI*VV) + i];
    __syncthreads();
    for (int i = threadIdx.x; i < 2*CR*VV; i += 256) {
        int sel = i / (CR*VV);
        int rv  = i - sel*(CR*VV);
        int r = rv / VV, v = rv - r*VV;
        const float* w = sel ? w2 : w1;
        float s = sel ? b2[r] : b1[r];
        #pragma unroll 8
        for (int c = 0; c < CI; c++) s += w[r*CI + c] * xm_s[c*VV + v];
        (sel ? g_x2 : g_x1)[n*(CR*VV) + rv] = s;
    }
}

// ---------------- K: aff = tanh(x1[u] - x2[v]) ----------------
__global__ void k_aff() {
    __shared__ float s1[CR*VV], s2[CR*VV];
    int n = blockIdx.x;
    for (int i = threadIdx.x; i < CR*VV; i += 256) {
        s1[i] = g_x1[n*(CR*VV) + i];
        s2[i] = g_x2[n*(CR*VV) + i];
    }
    __syncthreads();
    for (int i = threadIdx.x; i < CR*UV; i += 256) {
        int r = i / UV, uv = i - r*UV;
        int u = uv / VV, v = uv - u*VV;
        g_aff[n*(CR*UV) + i] = tanhf(s1[r*VV + u] - s2[r*VV + v]);
    }
}

// ---------------- K: attn = w4@aff + b4 + A ----------------
__global__ void k_attn(const float* __restrict__ w4, const float* __restrict__ b4,
                       const float* __restrict__ A) {
    __shared__ __align__(16) float w4s[64*CR];
    __shared__ __align__(16) float affs[CR*64];
    int n = blockIdx.z, cot = blockIdx.y, uvt = blockIdx.x;
    int co0 = cot*64, uv0 = uvt*64;
    int tx = threadIdx.x & 15, ty = threadIdx.x >> 4;

    for (int i = threadIdx.x; i < 64*CR; i += 256) w4s[i] = w4[co0*CR + i];
    for (int i = threadIdx.x; i < CR*64; i += 256) {
        int r = i >> 6, c = i & 63;
        affs[i] = (uv0 + c < UV) ? g_aff[n*(CR*UV) + r*UV + uv0 + c] : 0.f;
    }
    __syncthreads();

    float acc[4][4] = {};
    #pragma unroll
    for (int k = 0; k < CR; k++) {
        float4 b = *(const float4*)&affs[k*64 + tx*4];
        #pragma unroll
        for (int i = 0; i < 4; i++) {
            float a = w4s[(ty*4 + i)*CR + k];
            acc[i][0] += a*b.x; acc[i][1] += a*b.y;
            acc[i][2] += a*b.z; acc[i][3] += a*b.w;
        }
    }
    #pragma unroll
    for (int i = 0; i < 4; i++) {
        int co = co0 + ty*4 + i;
        float bb = b4[co];
        #pragma unroll
        for (int j = 0; j < 4; j++) {
            int uv = uv0 + tx*4 + j;
            if (uv < UV)
                g_attn[((size_t)n*CO + co)*UV + uv] = acc[i][j] + bb + A[uv];
        }
    }
}

// ---------------- K: w3 split ----------------
__global__ void k_w3cvt(const float* __restrict__ w3) {
    int i = blockIdx.x*1024 + threadIdx.x;
    float v = w3[i];
    __nv_bfloat16 hi = __float2bfloat16(v);
    g_bhi[i] = hi;
    g_blo[i] = __float2bfloat16(v - __bfloat162float(hi));
}

// ---------------- K: transpose + split x (50 x 8 x 64) ----------------
__global__ __launch_bounds__(256) void k_xcvt(const float* __restrict__ x) {
    __shared__ float tile[32][33];
    int n = blockIdx.z, c0 = blockIdx.y*32, tv0 = blockIdx.x*32;
    int tx = threadIdx.x & 31, ty = threadIdx.x >> 5;
    #pragma unroll
    for (int i = 0; i < 4; i++) {
        int c = c0 + ty + i*8;
        tile[ty + i*8][tx] = x[((size_t)(n*CI + c))*TV + tv0 + tx];
    }
    __syncthreads();
    int wtx = threadIdx.x & 15, wty = threadIdx.x >> 4;
    #pragma unroll
    for (int p = 0; p < 2; p++) {
        int tvl = wty + p*16;
        float v0 = tile[wtx*2][tvl], v1 = tile[wtx*2 + 1][tvl];
        __nv_bfloat16 h0 = __float2bfloat16(v0), h1 = __float2bfloat16(v1);
        __nv_bfloat162 hh; hh.x = h0; hh.y = h1;
        __nv_bfloat162 ll;
        ll.x = __float2bfloat16(v0 - __bfloat162float(h0));
        ll.y = __float2bfloat16(v1 - __bfloat162float(h1));
        size_t row = (size_t)n*TV + tv0 + tvl;
        *(__nv_bfloat162*)&g_ahi[row*CI + c0 + wtx*2] = hh;
        *(__nv_bfloat162*)&g_alo[row*CI + c0 + wtx*2] = ll;
    }
}

// ---------------- K: HMMA GEMM x3 = x @ w3^T + b3 (bf16 3-split, N=256 per CTA) ----------------
// 512 threads, 16 warps (4m x 4n), per-warp 32 rows x 64 co; K=256 in 4 chunks of 64.
#define SO_AH 0
#define SO_AL 16384
#define SO_BH 32768
#define SO_BL 65536
#define STAGE_BYTES 98304           // 96 KB per stage
#define MMA_SMEM (2*STAGE_BYTES)    // 192 KB

__global__ __launch_bounds__(512, 1) void k_mma(const float* __restrict__ b3) {
    extern __shared__ __align__(1024) char smem[];
    uint32_t sb = smem_u32(smem);
    int tid = threadIdx.x, lane = tid & 31, wid = tid >> 5;
    int tile = blockIdx.x;

    const __nv_bfloat16* abh = g_ahi + (size_t)tile*128*CI;
    const __nv_bfloat16* abl = g_alo + (size_t)tile*128*CI;

    auto load_chunk = [&](int kb, int stage) {
        uint32_t s0 = sb + stage*STAGE_BYTES;
        int q = tid & 7;
        int rbase = tid >> 3;       // 0..63
        // A: 128 rows x 128 B (hi+lo)
        const uint4* gah = (const uint4*)(abh + kb*64);
        const uint4* gal = (const uint4*)(abl + kb*64);
        #pragma unroll
        for (int it = 0; it < 2; it++) {
            int r = rbase + it*64;
            uint32_t so = swz((uint32_t)(r*128 + q*16));
            int gi = r*32 + q;
            CPA(s0 + SO_AH + so, gah + gi);
            CPA(s0 + SO_AL + so, gal + gi);
        }
        // B: 256 rows x 128 B (hi+lo)
        const uint4* gbh = (const uint4*)(g_bhi + kb*64);
        const uint4* gbl = (const uint4*)(g_blo + kb*64);
        #pragma unroll
        for (int it = 0; it < 4; it++) {
            int r = rbase + it*64;
            uint32_t so = swz((uint32_t)(r*128 + q*16));
            int gi = r*32 + q;
            CPA(s0 + SO_BH + so, gbh + gi);
            CPA(s0 + SO_BL + so, gbl + gi);
        }
        CPC();
    };

    int m0 = (wid & 3) * 32, n0 = (wid >> 2) * 64;
    float acc[2][8][4];
    #pragma unroll
    for (int mt = 0; mt < 2; mt++)
        #pragma unroll
        for (int nt = 0; nt < 8; nt++)
            #pragma unroll
            for (int k = 0; k < 4; k++) acc[mt][nt][k] = 0.f;

    load_chunk(0, 0);
    load_chunk(1, 1);

    int a_row = lane & 15;
    int a_seg = lane >> 4;
    int b_row = ((lane >> 4) & 1) * 8 + (lane & 7);
    int b_seg = (lane >> 3) & 1;

    #pragma unroll
    for (int kb = 0; kb < 4; kb++) {
        if (kb < 3) { CPW(1); } else { CPW(0); }
        __syncthreads();
        uint32_t s0 = sb + (kb & 1)*STAGE_BYTES;
        #pragma unroll
        for (int ks = 0; ks < 4; ks++) {
            uint32_t ah[2][4], al[2][4], bh[16], bl[16];
            #pragma unroll
            for (int mt = 0; mt < 2; mt++) {
                uint32_t off = swz((uint32_t)((m0 + mt*16 + a_row)*128 + ks*32 + a_seg*16));
                ldsm4(ah[mt][0], ah[mt][1], ah[mt][2], ah[mt][3], s0 + SO_AH + off);
                ldsm4(al[mt][0], al[mt][1], al[mt][2], al[mt][3], s0 + SO_AL + off);
            }
            #pragma unroll
            for (int np = 0; np < 4; np++) {
                uint32_t off = swz((uint32_t)((n0 + np*16 + b_row)*128 + ks*32 + b_seg*16));
                ldsm4(bh[np*4+0], bh[np*4+1], bh[np*4+2], bh[np*4+3], s0 + SO_BH + off);
                ldsm4(bl[np*4+0], bl[np*4+1], bl[np*4+2], bl[np*4+3], s0 + SO_BL + off);
            }
            #pragma unroll
            for (int mt = 0; mt < 2; mt++)
                #pragma unroll
                for (int nt = 0; nt < 8; nt++) {
                    mma16816(acc[mt][nt], ah[mt], &bh[nt*2]);
                    mma16816(acc[mt][nt], ah[mt], &bl[nt*2]);
                    mma16816(acc[mt][nt], al[mt], &bh[nt*2]);
                }
        }
        __syncthreads();
        if (kb < 2) load_chunk(kb + 2, kb & 1);
    }

    size_t rowg0 = (size_t)tile * 128;
    #pragma unroll
    for (int mt = 0; mt < 2; mt++) {
        int r0 = m0 + mt*16 + (lane >> 2);
        #pragma unroll
        for (int nt = 0; nt < 8; nt++) {
            int c = n0 + nt*8 + (lane & 3)*2;
            float2 bb = *(const float2*)(b3 + c);
            float2 v0, v1;
            v0.x = acc[mt][nt][0] + bb.x;  v0.y = acc[mt][nt][1] + bb.y;
            v1.x = acc[mt][nt][2] + bb.x;  v1.y = acc[mt][nt][3] + bb.y;
            *(float2*)(g_x3 + (rowg0 + r0    )*CO + c) = v0;
            *(float2*)(g_x3 + (rowg0 + r0 + 8)*CO + c) = v1;
        }
    }
}

// ---------------- K: out[n,co,t,v] = sum_u attn[n,co,u,v] * x3[n,(t,u),co] ----------------
__global__ __launch_bounds__(256) void k_out(float* __restrict__ out) {
    __shared__ __align__(16) float attn_s[8*700];
    __shared__ __align__(16) float x3_s[32*25*8];
    int n = blockIdx.y;
    int cot = blockIdx.x >> 1, tt = blockIdx.x & 1;
    int co0 = cot*8, t0 = tt*32;
    int tid = threadIdx.x;

    {
        const float* ab = g_attn + ((size_t)n*CO + co0)*UV;
        for (int i = tid; i < 8*700; i += 256) {
            int co = i / 700, rem = i - co*700;
            int u = rem / 28, v = rem - u*28;
            attn_s[i] = (v < VV) ? ab[co*UV + u*VV + v] : 0.f;
        }
        const float* xb = g_x3 + ((size_t)n*TV + t0*VV)*CO + co0;
        for (int i = tid; i < 32*25*8; i += 256) {
            int r = i >> 3, co = i & 7;
            x3_s[i] = xb[(size_t)r*CO + co];
        }
    }
    __syncthreads();

    int co = tid & 7, tl = tid >> 3;
    const float* arow = attn_s + co*700;
    const float* x3r  = x3_s + tl*200 + co;
    float4 o0={0,0,0,0},o1={0,0,0,0},o2={0,0,0,0},o3={0,0,0,0},o4={0,0,0,0},o5={0,0,0,0};
    float o24 = 0.f;
    for (int u = 0; u < 25; u++) {
        float xv = x3r[u*8];
        const float4* av = (const float4*)(arow + u*28);
        float4 a0=av[0],a1=av[1],a2=av[2],a3=av[3],a4=av[4],a5=av[5];
        float  a24 = arow[u*28 + 24];
        o0.x += xv*a0.x; o0.y += xv*a0.y; o0.z += xv*a0.z; o0.w += xv*a0.w;
        o1.x += xv*a1.x; o1.y += xv*a1.y; o1.z += xv*a1.z; o1.w += xv*a1.w;
        o2.x += xv*a2.x; o2.y += xv*a2.y; o2.z += xv*a2.z; o2.w += xv*a2.w;
        o3.x += xv*a3.x; o3.y += xv*a3.y; o3.z += xv*a3.z; o3.w += xv*a3.w;
        o4.x += xv*a4.x; o4.y += xv*a4.y; o4.z += xv*a4.z; o4.w += xv*a4.w;
        o5.x += xv*a5.x; o5.y += xv*a5.y; o5.z += xv*a5.z; o5.w += xv*a5.w;
        o24  += xv*a24;
    }
    float* op = out + (((size_t)(n*CO + co0 + co))*TT + t0 + tl)*VV;
    op[0]=o0.x;  op[1]=o0.y;  op[2]=o0.z;  op[3]=o0.w;
    op[4]=o1.x;  op[5]=o1.y;  op[6]=o1.z;  op[7]=o1.w;
    op[8]=o2.x;  op[9]=o2.y;  op[10]=o2.z; op[11]=o2.w;
    op[12]=o3.x; op[13]=o3.y; op[14]=o3.z; op[15]=o3.w;
    op[16]=o4.x; op[17]=o4.y; op[18]=o4.z; op[19]=o4.w;
    op[20]=o5.x; op[21]=o5.y; op[22]=o5.z; op[23]=o5.w;
    op[24]=o24;
}

// ---------------- launch (k_mma placed 4th to get its ncu capture) ----------------
extern "C" void kernel_launch(void* const* d_in, const int* in_sizes, int n_in,
                              void* d_out, int out_size) {
    const float* x  = (const float*)d_in[0];
    const float* A  = (const float*)d_in[1];
    const float* w1 = (const float*)d_in[2];
    const float* b1 = (const float*)d_in[3];
    const float* w2 = (const float*)d_in[4];
    const float* b2 = (const float*)d_in[5];
    const float* w3 = (const float*)d_in[6];
    const float* b3 = (const float*)d_in[7];
    const float* w4 = (const float*)d_in[8];
    const float* b4 = (const float*)d_in[9];
    float* out = (float*)d_out;

    cudaFuncSetAttribute(k_mma, cudaFuncAttributeMaxDynamicSharedMemorySize, MMA_SMEM);

    k_w3cvt<<<64, 1024>>>(w3);                 // 1
    k_xcvt <<<dim3(50, 8, 64), 256>>>(x);      // 2
    k_xm   <<<dim3(64, 64), 256>>>(x);         // 3
    k_mma  <<<NTILES, 512, MMA_SMEM>>>(b3);    // 4  <-- profiled slot
    k_x12  <<<64, 256>>>(w1, b1, w2, b2);      // 5
    k_aff  <<<64, 256>>>();                    // 6
    k_attn <<<dim3(10, 4, 64), 256>>>(w4, b4, A); // 7
    k_out  <<<dim3(64, 64), 256>>>(out);       // 8
}

// round 8
// speedup vs baseline: 1.4181x; 1.0446x over previous
#include <cuda_runtime.h>
#include <cuda_bf16.h>
#include <cstdint>

#define NN 64
#define CI 256
#define CO 256
#define CR 32
#define TT 64
#define VV 25
#define TV 1600   // T*V
#define UV 625    // V*V
#define NROWS (NN*TV)       // 102400

// ---------------- scratch ----------------
__device__ float g_xm[NN*CI*VV];
__device__ float g_x1[NN*CR*VV];
__device__ float g_x2[NN*CR*VV];
__device__ float g_aff[NN*CR*UV];
__device__ float g_attn[NN*CO*UV];     // (n, co, u*25+v)
__device__ __nv_bfloat16 g_bhi[CO*CI]; // bf16(w3)    [co, c]
__device__ __nv_bfloat16 g_blo[CO*CI];
__device__ float g_x3[(size_t)NROWS*CO]; // [row=(n,t,u), co]

// ---------------- helpers ----------------
__device__ __forceinline__ uint32_t smem_u32(const void* p) {
    uint32_t a;
    asm("{ .reg .u64 t; cvta.to.shared.u64 t, %1; cvt.u32.u64 %0, t; }" : "=r"(a) : "l"(p));
    return a;
}
#define CPA(dst, src) asm volatile("cp.async.cg.shared.global [%0], [%1], 16;" \
                                   :: "r"(dst), "l"(src) : "memory")
#define CPC() asm volatile("cp.async.commit_group;" ::: "memory")
#define CPW(n) asm volatile("cp.async.wait_group %0;" :: "n"(n) : "memory")

__device__ __forceinline__ void ldsm4(uint32_t& r0, uint32_t& r1, uint32_t& r2, uint32_t& r3,
                                      uint32_t a) {
    asm volatile("ldmatrix.sync.aligned.m8n8.x4.shared.b16 {%0,%1,%2,%3}, [%4];"
                 : "=r"(r0), "=r"(r1), "=r"(r2), "=r"(r3) : "r"(a));
}
__device__ __forceinline__ void mma16816(float* d, const uint32_t* a, const uint32_t* b) {
    asm volatile("mma.sync.aligned.m16n8k16.row.col.f32.bf16.bf16.f32 "
                 "{%0,%1,%2,%3}, {%4,%5,%6,%7}, {%8,%9}, {%0,%1,%2,%3};"
                 : "+f"(d[0]), "+f"(d[1]), "+f"(d[2]), "+f"(d[3])
                 : "r"(a[0]), "r"(a[1]), "r"(a[2]), "r"(a[3]), "r"(b[0]), "r"(b[1]));
}

// ---------------- K: xm = mean_t x ----------------
__global__ void k_xm(const float* __restrict__ x) {
    __shared__ float sx[4*TV];
    int n = blockIdx.y, cc = blockIdx.x;
    const float* xb = x + ((size_t)(n*CI + cc*4))*TV;
    for (int i = threadIdx.x; i < 4*TV; i += 256) sx[i] = xb[i];
    __syncthreads();
    if (threadIdx.x < 100) {
        int c = threadIdx.x / VV, v = threadIdx.x - c*VV;
        float s = 0.f;
        #pragma unroll
        for (int t = 0; t < TT; t++) s += sx[c*TV + t*VV + v];
        g_xm[n*(CI*VV) + cc*100 + threadIdx.x] = s * (1.0f/64.0f);
    }
}

// ---------------- K: x1/x2 ----------------
__global__ void k_x12(const float* __restrict__ w1, const float* __restrict__ b1,
                      const float* __restrict__ w2, const float* __restrict__ b2) {
    __shared__ float xm_s[CI*VV];
    int n = blockIdx.x;
    for (int i = threadIdx.x; i < CI*VV; i += 256) xm_s[i] = g_xm[n*(CI*VV) + i];
    __syncthreads();
    for (int i = threadIdx.x; i < 2*CR*VV; i += 256) {
        int sel = i / (CR*VV);
        int rv  = i - sel*(CR*VV);
        int r = rv / VV, v = rv - r*VV;
        const float* w = sel ? w2 : w1;
        float s = sel ? b2[r] : b1[r];
        #pragma unroll 8
        for (int c = 0; c < CI; c++) s += w[r*CI + c] * xm_s[c*VV + v];
        (sel ? g_x2 : g_x1)[n*(CR*VV) + rv] = s;
    }
}

// ---------------- K: aff = tanh(x1[u] - x2[v]) ----------------
__global__ void k_aff() {
    __shared__ float s1[CR*VV], s2[CR*VV];
    int n = blockIdx.x;
    for (int i = threadIdx.x; i < CR*VV; i += 256) {
        s1[i] = g_x1[n*(CR*VV) + i];
        s2[i] = g_x2[n*(CR*VV) + i];
    }
    __syncthreads();
    for (int i = threadIdx.x; i < CR*UV; i += 256) {
        int r = i / UV, uv = i - r*UV;
        int u = uv / VV, v = uv - u*VV;
        g_aff[n*(CR*UV) + i] = tanhf(s1[r*VV + u] - s2[r*VV + v]);
    }
}

// ---------------- K: attn = w4@aff + b4 + A ----------------
__global__ void k_attn(const float* __restrict__ w4, const float* __restrict__ b4,
                       const float* __restrict__ A) {
    __shared__ __align__(16) float w4s[64*CR];
    __shared__ __align__(16) float affs[CR*64];
    int n = blockIdx.z, cot = blockIdx.y, uvt = blockIdx.x;
    int co0 = cot*64, uv0 = uvt*64;
    int tx = threadIdx.x & 15, ty = threadIdx.x >> 4;

    for (int i = threadIdx.x; i < 64*CR; i += 256) w4s[i] = w4[co0*CR + i];
    for (int i = threadIdx.x; i < CR*64; i += 256) {
        int r = i >> 6, c = i & 63;
        affs[i] = (uv0 + c < UV) ? g_aff[n*(CR*UV) + r*UV + uv0 + c] : 0.f;
    }
    __syncthreads();

    float acc[4][4] = {};
    #pragma unroll
    for (int k = 0; k < CR; k++) {
        float4 b = *(const float4*)&affs[k*64 + tx*4];
        #pragma unroll
        for (int i = 0; i < 4; i++) {
            float a = w4s[(ty*4 + i)*CR + k];
            acc[i][0] += a*b.x; acc[i][1] += a*b.y;
            acc[i][2] += a*b.z; acc[i][3] += a*b.w;
        }
    }
    #pragma unroll
    for (int i = 0; i < 4; i++) {
        int co = co0 + ty*4 + i;
        float bb = b4[co];
        #pragma unroll
        for (int j = 0; j < 4; j++) {
            int uv = uv0 + tx*4 + j;
            if (uv < UV)
                g_attn[((size_t)n*CO + co)*UV + uv] = acc[i][j] + bb + A[uv];
        }
    }
}

// ---------------- K: w3 split ----------------
__global__ void k_w3cvt(const float* __restrict__ w3) {
    int i = blockIdx.x*1024 + threadIdx.x;
    float v = w3[i];
    __nv_bfloat16 hi = __float2bfloat16(v);
    g_bhi[i] = hi;
    g_blo[i] = __float2bfloat16(v - __bfloat162float(hi));
}

// ---------------- K: fused convert + HMMA GEMM  x3 = x @ w3^T + b3 ----------------
// grid (13 tiles, 64 n); CTA: 128 tv rows x 256 co, K=256 in 8 chunks of 32.
// x fp32 loaded directly (coalesced), hi/lo bf16 split + transpose done in smem.
// smem: XF (fp32 [c][tv]) x2 @16KB | A (bf16 [tv][c], 80B stride, hi+lo) x2 @20KB
//       B (bf16 [co][c], 80B stride, hi+lo) x3 @40KB    total 192KB
#define XF_OFF 0
#define XF_SZ  16384
#define A_OFF  32768
#define A_SZ   20480
#define AL_OFF 10240
#define B_OFF  73728
#define B_SZ   40960
#define BL_OFF 20480
#define MMA_SMEM 196608

__global__ __launch_bounds__(512, 1) void k_mma(const float* __restrict__ x,
                                                const float* __restrict__ b3) {
    extern __shared__ __align__(1024) char smem[];
    uint32_t sb = smem_u32(smem);
    int tid = threadIdx.x, lane = tid & 31, wid = tid >> 5;
    int tile = blockIdx.x, n = blockIdx.y;
    int tv0 = tile * 128;
    int rows = (TV - tv0 >= 128) ? 128 : (TV - tv0);   // 128, last tile: 64
    const float* xb = x + ((size_t)n*CI)*TV + tv0;

    auto loadX = [&](int kb, int s) {
        uint32_t xo = sb + XF_OFF + s*XF_SZ;
        #pragma unroll
        for (int it = 0; it < 2; it++) {
            int idx = tid + it*512;           // 1024 = 32 c x 32 q
            int c = idx >> 5, q = idx & 31;
            int tq = (q*4 < rows) ? q : 0;    // clamp for half tile
            CPA(xo + c*512 + q*16, xb + (size_t)(kb*32 + c)*TV + tq*4);
        }
    };
    auto loadB = [&](int kb, int bs) {
        uint32_t bo = sb + B_OFF + bs*B_SZ;
        #pragma unroll
        for (int it = 0; it < 4; it++) {
            int idx = tid + it*512;           // 2048 = 2 splits x 256 co x 4 q
            int split = idx >> 10, r = idx & 1023;
            int co = r >> 2, q = r & 3;
            const __nv_bfloat16* src = (split ? g_blo : g_bhi) + co*256 + kb*32 + q*8;
            CPA(bo + split*BL_OFF + co*80 + q*16, src);
        }
    };
    auto convert = [&](int s) {
        const char* xf = smem + XF_OFF + s*XF_SZ;
        char* ad = smem + A_OFF + s*A_SZ;
        int tv = tid & 127, cg = tid >> 7;    // cg: c-group of 8
        const float* col = (const float*)(xf + cg*8*512 + tv*4);
        uint32_t hi[4], lo[4];
        #pragma unroll
        for (int j = 0; j < 4; j++) {
            float v0 = col[(2*j)*128];        // c stride = 512B = 128 floats
            float v1 = col[(2*j+1)*128];
            __nv_bfloat16 h0 = __float2bfloat16(v0), h1 = __float2bfloat16(v1);
            __nv_bfloat162 hh; hh.x = h0; hh.y = h1;
            __nv_bfloat162 ll;
            ll.x = __float2bfloat16(v0 - __bfloat162float(h0));
            ll.y = __float2bfloat16(v1 - __bfloat162float(h1));
            hi[j] = *(uint32_t*)&hh;
            lo[j] = *(uint32_t*)&ll;
        }
        *(uint4*)(ad + tv*80 + cg*16)          = make_uint4(hi[0],hi[1],hi[2],hi[3]);
        *(uint4*)(ad + AL_OFF + tv*80 + cg*16) = make_uint4(lo[0],lo[1],lo[2],lo[3]);
    };

    loadX(0, 0); loadB(0, 0); CPC();
    loadX(1, 1); loadB(1, 1); CPC();

    int m0 = (wid & 3)*32, n0 = (wid >> 2)*64;
    float acc[2][8][4];
    #pragma unroll
    for (int mt = 0; mt < 2; mt++)
        #pragma unroll
        for (int nt = 0; nt < 8; nt++)
            #pragma unroll
            for (int k = 0; k < 4; k++) acc[mt][nt][k] = 0.f;

    int a_row = lane & 15, a_seg = lane >> 4;
    int b_row = ((lane >> 4) & 1)*8 + (lane & 7), b_seg = (lane >> 3) & 1;

    #pragma unroll
    for (int kb = 0; kb < 8; kb++) {
        if (kb < 7) { CPW(1); } else { CPW(0); }
        __syncthreads();
        convert(kb & 1);
        __syncthreads();
        if (kb < 6) { loadX(kb + 2, kb & 1); loadB(kb + 2, (kb + 2) % 3); CPC(); }
        uint32_t ao = sb + A_OFF + (kb & 1)*A_SZ;
        uint32_t bo = sb + B_OFF + (kb % 3)*B_SZ;
        #pragma unroll
        for (int ks = 0; ks < 2; ks++) {
            uint32_t ah[2][4], al[2][4], bh[16], bl[16];
            #pragma unroll
            for (int mt = 0; mt < 2; mt++) {
                uint32_t off = (uint32_t)((m0 + mt*16 + a_row)*80 + ks*32 + a_seg*16);
                ldsm4(ah[mt][0], ah[mt][1], ah[mt][2], ah[mt][3], ao + off);
                ldsm4(al[mt][0], al[mt][1], al[mt][2], al[mt][3], ao + AL_OFF + off);
            }
            #pragma unroll
            for (int np = 0; np < 4; np++) {
                uint32_t off = (uint32_t)((n0 + np*16 + b_row)*80 + ks*32 + b_seg*16);
                ldsm4(bh[np*4+0], bh[np*4+1], bh[np*4+2], bh[np*4+3], bo + off);
                ldsm4(bl[np*4+0], bl[np*4+1], bl[np*4+2], bl[np*4+3], bo + BL_OFF + off);
            }
            #pragma unroll
            for (int mt = 0; mt < 2; mt++)
                #pragma unroll
                for (int nt = 0; nt < 8; nt++) {
                    mma16816(acc[mt][nt], ah[mt], &bh[nt*2]);
                    mma16816(acc[mt][nt], ah[mt], &bl[nt*2]);
                    mma16816(acc[mt][nt], al[mt], &bh[nt*2]);
                }
        }
    }

    size_t rowg0 = (size_t)n*TV + tv0;
    #pragma unroll
    for (int mt = 0; mt < 2; mt++) {
        int r0 = m0 + mt*16 + (lane >> 2);
        #pragma unroll
        for (int nt = 0; nt < 8; nt++) {
            int c = n0 + nt*8 + (lane & 3)*2;
            float2 bb = *(const float2*)(b3 + c);
            float2 v0, v1;
            v0.x = acc[mt][nt][0] + bb.x;  v0.y = acc[mt][nt][1] + bb.y;
            v1.x = acc[mt][nt][2] + bb.x;  v1.y = acc[mt][nt][3] + bb.y;
            if (r0 < rows)     *(float2*)(g_x3 + (rowg0 + r0    )*CO + c) = v0;
            if (r0 + 8 < rows) *(float2*)(g_x3 + (rowg0 + r0 + 8)*CO + c) = v1;
        }
    }
}

// ---------------- K: out[n,co,t,v] = sum_u attn[n,co,u,v] * x3[n,(t,u),co] ----------------
__global__ __launch_bounds__(256) void k_out(float* __restrict__ out) {
    __shared__ __align__(16) float attn_s[8*700];
    __shared__ __align__(16) float x3_s[32*25*8];
    int n = blockIdx.y;
    int cot = blockIdx.x >> 1, tt = blockIdx.x & 1;
    int co0 = cot*8, t0 = tt*32;
    int tid = threadIdx.x;

    {
        const float* ab = g_attn + ((size_t)n*CO + co0)*UV;
        for (int i = tid; i < 8*700; i += 256) {
            int co = i / 700, rem = i - co*700;
            int u = rem / 28, v = rem - u*28;
            attn_s[i] = (v < VV) ? ab[co*UV + u*VV + v] : 0.f;
        }
        const float* xb = g_x3 + ((size_t)n*TV + t0*VV)*CO + co0;
        for (int i = tid; i < 32*25*8; i += 256) {
            int r = i >> 3, co = i & 7;
            x3_s[i] = xb[(size_t)r*CO + co];
        }
    }
    __syncthreads();

    int co = tid & 7, tl = tid >> 3;
    const float* arow = attn_s + co*700;
    const float* x3r  = x3_s + tl*200 + co;
    float4 o0={0,0,0,0},o1={0,0,0,0},o2={0,0,0,0},o3={0,0,0,0},o4={0,0,0,0},o5={0,0,0,0};
    float o24 = 0.f;
    for (int u = 0; u < 25; u++) {
        float xv = x3r[u*8];
        const float4* av = (const float4*)(arow + u*28);
        float4 a0=av[0],a1=av[1],a2=av[2],a3=av[3],a4=av[4],a5=av[5];
        float  a24 = arow[u*28 + 24];
        o0.x += xv*a0.x; o0.y += xv*a0.y; o0.z += xv*a0.z; o0.w += xv*a0.w;
        o1.x += xv*a1.x; o1.y += xv*a1.y; o1.z += xv*a1.z; o1.w += xv*a1.w;
        o2.x += xv*a2.x; o2.y += xv*a2.y; o2.z += xv*a2.z; o2.w += xv*a2.w;
        o3.x += xv*a3.x; o3.y += xv*a3.y; o3.z += xv*a3.z; o3.w += xv*a3.w;
        o4.x += xv*a4.x; o4.y += xv*a4.y; o4.z += xv*a4.z; o4.w += xv*a4.w;
        o5.x += xv*a5.x; o5.y += xv*a5.y; o5.z += xv*a5.z; o5.w += xv*a5.w;
        o24  += xv*a24;
    }
    float* op = out + (((size_t)(n*CO + co0 + co))*TT + t0 + tl)*VV;
    op[0]=o0.x;  op[1]=o0.y;  op[2]=o0.z;  op[3]=o0.w;
    op[4]=o1.x;  op[5]=o1.y;  op[6]=o1.z;  op[7]=o1.w;
    op[8]=o2.x;  op[9]=o2.y;  op[10]=o2.z; op[11]=o2.w;
    op[12]=o3.x; op[13]=o3.y; op[14]=o3.z; op[15]=o3.w;
    op[16]=o4.x; op[17]=o4.y; op[18]=o4.z; op[19]=o4.w;
    op[20]=o5.x; op[21]=o5.y; op[22]=o5.z; op[23]=o5.w;
    op[24]=o24;
}

// ---------------- launch (k_mma in profiled slot 4) ----------------
extern "C" void kernel_launch(void* const* d_in, const int* in_sizes, int n_in,
                              void* d_out, int out_size) {
    const float* x  = (const float*)d_in[0];
    const float* A  = (const float*)d_in[1];
    const float* w1 = (const float*)d_in[2];
    const float* b1 = (const float*)d_in[3];
    const float* w2 = (const float*)d_in[4];
    const float* b2 = (const float*)d_in[5];
    const float* w3 = (const float*)d_in[6];
    const float* b3 = (const float*)d_in[7];
    const float* w4 = (const float*)d_in[8];
    const float* b4 = (const float*)d_in[9];
    float* out = (float*)d_out;

    cudaFuncSetAttribute(k_mma, cudaFuncAttributeMaxDynamicSharedMemorySize, MMA_SMEM);

    k_w3cvt<<<64, 1024>>>(w3);                    // 1
    k_xm   <<<dim3(64, 64), 256>>>(x);            // 2
    k_x12  <<<64, 256>>>(w1, b1, w2, b2);         // 3
    k_mma  <<<dim3(13, 64), 512, MMA_SMEM>>>(x, b3); // 4  <-- profiled
    k_aff  <<<64, 256>>>();                       // 5
    k_attn <<<dim3(10, 4, 64), 256>>>(w4, b4, A); // 6
    k_out  <<<dim3(64, 64), 256>>>(out);          // 7
}

// round 9
// speedup vs baseline: 1.6361x; 1.1537x over previous
#include <cuda_runtime.h>
#include <cuda_bf16.h>
#include <cstdint>

#define NN 64
#define CI 256
#define CO 256
#define CR 32
#define TT 64
#define VV 25
#define TV 1600   // T*V
#define UV 625    // V*V
#define NROWS (NN*TV)       // 102400

// ---------------- scratch ----------------
__device__ float g_xm[NN*CI*VV];
__device__ float g_x1[NN*CR*VV];
__device__ float g_x2[NN*CR*VV];
__device__ float g_aff[NN*CR*UV];
__device__ float g_attn[NN*CO*UV];     // (n, co, u*25+v)
__device__ __nv_bfloat16 g_bhi[CO*CI]; // bf16(w3)    [co, c]
__device__ __nv_bfloat16 g_blo[CO*CI];
__device__ float g_x3[(size_t)NROWS*CO]; // [row=(n,t,u), co]

// ---------------- helpers ----------------
__device__ __forceinline__ uint32_t smem_u32(const void* p) {
    uint32_t a;
    asm("{ .reg .u64 t; cvta.to.shared.u64 t, %1; cvt.u32.u64 %0, t; }" : "=r"(a) : "l"(p));
    return a;
}
#define CPA(dst, src) asm volatile("cp.async.cg.shared.global [%0], [%1], 16;" \
                                   :: "r"(dst), "l"(src) : "memory")
#define CPC() asm volatile("cp.async.commit_group;" ::: "memory")
#define CPW(n) asm volatile("cp.async.wait_group %0;" :: "n"(n) : "memory")

__device__ __forceinline__ void ldsm4(uint32_t& r0, uint32_t& r1, uint32_t& r2, uint32_t& r3,
                                      uint32_t a) {
    asm volatile("ldmatrix.sync.aligned.m8n8.x4.shared.b16 {%0,%1,%2,%3}, [%4];"
                 : "=r"(r0), "=r"(r1), "=r"(r2), "=r"(r3) : "r"(a));
}
__device__ __forceinline__ void mma16816(float* d, const uint32_t* a, const uint32_t* b) {
    asm volatile("mma.sync.aligned.m16n8k16.row.col.f32.bf16.bf16.f32 "
                 "{%0,%1,%2,%3}, {%4,%5,%6,%7}, {%8,%9}, {%0,%1,%2,%3};"
                 : "+f"(d[0]), "+f"(d[1]), "+f"(d[2]), "+f"(d[3])
                 : "r"(a[0]), "r"(a[1]), "r"(a[2]), "r"(a[3]), "r"(b[0]), "r"(b[1]));
}

// ---------------- K: xm = mean_t x ----------------
__global__ void k_xm(const float* __restrict__ x) {
    __shared__ float sx[4*TV];
    int n = blockIdx.y, cc = blockIdx.x;
    const float* xb = x + ((size_t)(n*CI + cc*4))*TV;
    for (int i = threadIdx.x; i < 4*TV; i += 256) sx[i] = xb[i];
    __syncthreads();
    if (threadIdx.x < 100) {
        int c = threadIdx.x / VV, v = threadIdx.x - c*VV;
        float s = 0.f;
        #pragma unroll
        for (int t = 0; t < TT; t++) s += sx[c*TV + t*VV + v];
        g_xm[n*(CI*VV) + cc*100 + threadIdx.x] = s * (1.0f/64.0f);
    }
}

// ---------------- K: x1/x2 ----------------
__global__ void k_x12(const float* __restrict__ w1, const float* __restrict__ b1,
                      const float* __restrict__ w2, const float* __restrict__ b2) {
    __shared__ float xm_s[CI*VV];
    int n = blockIdx.x;
    for (int i = threadIdx.x; i < CI*VV; i += 256) xm_s[i] = g_xm[n*(CI*VV) + i];
    __syncthreads();
    for (int i = threadIdx.x; i < 2*CR*VV; i += 256) {
        int sel = i / (CR*VV);
        int rv  = i - sel*(CR*VV);
        int r = rv / VV, v = rv - r*VV;
        const float* w = sel ? w2 : w1;
        float s = sel ? b2[r] : b1[r];
        #pragma unroll 8
        for (int c = 0; c < CI; c++) s += w[r*CI + c] * xm_s[c*VV + v];
        (sel ? g_x2 : g_x1)[n*(CR*VV) + rv] = s;
    }
}

// ---------------- K: aff = tanh(x1[u] - x2[v]) ----------------
__global__ void k_aff() {
    __shared__ float s1[CR*VV], s2[CR*VV];
    int n = blockIdx.x;
    for (int i = threadIdx.x; i < CR*VV; i += 256) {
        s1[i] = g_x1[n*(CR*VV) + i];
        s2[i] = g_x2[n*(CR*VV) + i];
    }
    __syncthreads();
    for (int i = threadIdx.x; i < CR*UV; i += 256) {
        int r = i / UV, uv = i - r*UV;
        int u = uv / VV, v = uv - u*VV;
        g_aff[n*(CR*UV) + i] = tanhf(s1[r*VV + u] - s2[r*VV + v]);
    }
}

// ---------------- K: attn = w4@aff + b4 + A ----------------
__global__ void k_attn(const float* __restrict__ w4, const float* __restrict__ b4,
                       const float* __restrict__ A) {
    __shared__ __align__(16) float w4s[64*CR];
    __shared__ __align__(16) float affs[CR*64];
    int n = blockIdx.z, cot = blockIdx.y, uvt = blockIdx.x;
    int co0 = cot*64, uv0 = uvt*64;
    int tx = threadIdx.x & 15, ty = threadIdx.x >> 4;

    for (int i = threadIdx.x; i < 64*CR; i += 256) w4s[i] = w4[co0*CR + i];
    for (int i = threadIdx.x; i < CR*64; i += 256) {
        int r = i >> 6, c = i & 63;
        affs[i] = (uv0 + c < UV) ? g_aff[n*(CR*UV) + r*UV + uv0 + c] : 0.f;
    }
    __syncthreads();

    float acc[4][4] = {};
    #pragma unroll
    for (int k = 0; k < CR; k++) {
        float4 b = *(const float4*)&affs[k*64 + tx*4];
        #pragma unroll
        for (int i = 0; i < 4; i++) {
            float a = w4s[(ty*4 + i)*CR + k];
            acc[i][0] += a*b.x; acc[i][1] += a*b.y;
            acc[i][2] += a*b.z; acc[i][3] += a*b.w;
        }
    }
    #pragma unroll
    for (int i = 0; i < 4; i++) {
        int co = co0 + ty*4 + i;
        float bb = b4[co];
        #pragma unroll
        for (int j = 0; j < 4; j++) {
            int uv = uv0 + tx*4 + j;
            if (uv < UV)
                g_attn[((size_t)n*CO + co)*UV + uv] = acc[i][j] + bb + A[uv];
        }
    }
}

// ---------------- K: w3 split ----------------
__global__ void k_w3cvt(const float* __restrict__ w3) {
    int i = blockIdx.x*1024 + threadIdx.x;
    float v = w3[i];
    __nv_bfloat16 hi = __float2bfloat16(v);
    g_bhi[i] = hi;
    g_blo[i] = __float2bfloat16(v - __bfloat162float(hi));
}

// ---------------- K: fused convert + HMMA GEMM  x3 = x @ w3^T + b3 ----------------
#define XF_OFF 0
#define XF_SZ  16384
#define A_OFF  32768
#define A_SZ   20480
#define AL_OFF 10240
#define B_OFF  73728
#define B_SZ   40960
#define BL_OFF 20480
#define MMA_SMEM 196608

__global__ __launch_bounds__(512, 1) void k_mma(const float* __restrict__ x,
                                                const float* __restrict__ b3) {
    extern __shared__ __align__(1024) char smem[];
    uint32_t sb = smem_u32(smem);
    int tid = threadIdx.x, lane = tid & 31, wid = tid >> 5;
    int tile = blockIdx.x, n = blockIdx.y;
    int tv0 = tile * 128;
    int rows = (TV - tv0 >= 128) ? 128 : (TV - tv0);
    const float* xb = x + ((size_t)n*CI)*TV + tv0;

    auto loadX = [&](int kb, int s) {
        uint32_t xo = sb + XF_OFF + s*XF_SZ;
        #pragma unroll
        for (int it = 0; it < 2; it++) {
            int idx = tid + it*512;
            int c = idx >> 5, q = idx & 31;
            int tq = (q*4 < rows) ? q : 0;
            CPA(xo + c*512 + q*16, xb + (size_t)(kb*32 + c)*TV + tq*4);
        }
    };
    auto loadB = [&](int kb, int bs) {
        uint32_t bo = sb + B_OFF + bs*B_SZ;
        #pragma unroll
        for (int it = 0; it < 4; it++) {
            int idx = tid + it*512;
            int split = idx >> 10, r = idx & 1023;
            int co = r >> 2, q = r & 3;
            const __nv_bfloat16* src = (split ? g_blo : g_bhi) + co*256 + kb*32 + q*8;
            CPA(bo + split*BL_OFF + co*80 + q*16, src);
        }
    };
    auto convert = [&](int s) {
        const char* xf = smem + XF_OFF + s*XF_SZ;
        char* ad = smem + A_OFF + s*A_SZ;
        int tv = tid & 127, cg = tid >> 7;
        const float* col = (const float*)(xf + cg*8*512 + tv*4);
        uint32_t hi[4], lo[4];
        #pragma unroll
        for (int j = 0; j < 4; j++) {
            float v0 = col[(2*j)*128];
            float v1 = col[(2*j+1)*128];
            __nv_bfloat16 h0 = __float2bfloat16(v0), h1 = __float2bfloat16(v1);
            __nv_bfloat162 hh; hh.x = h0; hh.y = h1;
            __nv_bfloat162 ll;
            ll.x = __float2bfloat16(v0 - __bfloat162float(h0));
            ll.y = __float2bfloat16(v1 - __bfloat162float(h1));
            hi[j] = *(uint32_t*)&hh;
            lo[j] = *(uint32_t*)&ll;
        }
        *(uint4*)(ad + tv*80 + cg*16)          = make_uint4(hi[0],hi[1],hi[2],hi[3]);
        *(uint4*)(ad + AL_OFF + tv*80 + cg*16) = make_uint4(lo[0],lo[1],lo[2],lo[3]);
    };

    loadX(0, 0); loadB(0, 0); CPC();
    loadX(1, 1); loadB(1, 1); CPC();

    int m0 = (wid & 3)*32, n0 = (wid >> 2)*64;
    float acc[2][8][4];
    #pragma unroll
    for (int mt = 0; mt < 2; mt++)
        #pragma unroll
        for (int nt = 0; nt < 8; nt++)
            #pragma unroll
            for (int k = 0; k < 4; k++) acc[mt][nt][k] = 0.f;

    int a_row = lane & 15, a_seg = lane >> 4;
    int b_row = ((lane >> 4) & 1)*8 + (lane & 7), b_seg = (lane >> 3) & 1;

    #pragma unroll
    for (int kb = 0; kb < 8; kb++) {
        if (kb < 7) { CPW(1); } else { CPW(0); }
        __syncthreads();
        convert(kb & 1);
        __syncthreads();
        if (kb < 6) { loadX(kb + 2, kb & 1); loadB(kb + 2, (kb + 2) % 3); CPC(); }
        uint32_t ao = sb + A_OFF + (kb & 1)*A_SZ;
        uint32_t bo = sb + B_OFF + (kb % 3)*B_SZ;
        #pragma unroll
        for (int ks = 0; ks < 2; ks++) {
            uint32_t ah[2][4], al[2][4], bh[16], bl[16];
            #pragma unroll
            for (int mt = 0; mt < 2; mt++) {
                uint32_t off = (uint32_t)((m0 + mt*16 + a_row)*80 + ks*32 + a_seg*16);
                ldsm4(ah[mt][0], ah[mt][1], ah[mt][2], ah[mt][3], ao + off);
                ldsm4(al[mt][0], al[mt][1], al[mt][2], al[mt][3], ao + AL_OFF + off);
            }
            #pragma unroll
            for (int np = 0; np < 4; np++) {
                uint32_t off = (uint32_t)((n0 + np*16 + b_row)*80 + ks*32 + b_seg*16);
                ldsm4(bh[np*4+0], bh[np*4+1], bh[np*4+2], bh[np*4+3], bo + off);
                ldsm4(bl[np*4+0], bl[np*4+1], bl[np*4+2], bl[np*4+3], bo + BL_OFF + off);
            }
            #pragma unroll
            for (int mt = 0; mt < 2; mt++)
                #pragma unroll
                for (int nt = 0; nt < 8; nt++) {
                    mma16816(acc[mt][nt], ah[mt], &bh[nt*2]);
                    mma16816(acc[mt][nt], ah[mt], &bl[nt*2]);
                    mma16816(acc[mt][nt], al[mt], &bh[nt*2]);
                }
        }
    }

    size_t rowg0 = (size_t)n*TV + tv0;
    #pragma unroll
    for (int mt = 0; mt < 2; mt++) {
        int r0 = m0 + mt*16 + (lane >> 2);
        #pragma unroll
        for (int nt = 0; nt < 8; nt++) {
            int c = n0 + nt*8 + (lane & 3)*2;
            float2 bb = *(const float2*)(b3 + c);
            float2 v0, v1;
            v0.x = acc[mt][nt][0] + bb.x;  v0.y = acc[mt][nt][1] + bb.y;
            v1.x = acc[mt][nt][2] + bb.x;  v1.y = acc[mt][nt][3] + bb.y;
            if (r0 < rows)     *(float2*)(g_x3 + (rowg0 + r0    )*CO + c) = v0;
            if (r0 + 8 < rows) *(float2*)(g_x3 + (rowg0 + r0 + 8)*CO + c) = v1;
        }
    }
}

// ---------------- K: out — CTA (n, 8co, all 64 t); lane=v, attn cached in regs ----------------
// smem: attn_s 8*700 (22.4KB) + x3_s [t][u][co] 64*25*8 (51.2KB) = 73.6KB -> 2 CTA/SM
__global__ __launch_bounds__(512) void k_out(float* __restrict__ out) {
    __shared__ __align__(16) float attn_s[8*700];
    __shared__ __align__(16) float x3_s[TT*VV*8];
    int n = blockIdx.y, co0 = blockIdx.x*8;
    int tid = threadIdx.x;

    const float* ab = g_attn + ((size_t)n*CO + co0)*UV;
    for (int i = tid; i < 8*700; i += 512) {
        int co = i / 700, rem = i - co*700;
        int u = rem / 28, v = rem - u*28;
        attn_s[i] = (v < VV) ? ab[co*UV + u*VV + v] : 0.f;
    }
    const float* xb = g_x3 + ((size_t)n*TV)*CO + co0;
    for (int i = tid; i < TT*VV*8; i += 512) {
        int r = i >> 3, co = i & 7;      // r = t*25+u
        x3_s[i] = xb[(size_t)r*CO + co];
    }
    __syncthreads();

    int lane = tid & 31, wid = tid >> 5;
    int co = wid & 7, tg = wid >> 3;     // 8 co x 2 t-groups
    // preload attn row for this co into registers: a[u] = attn[co][u][v=lane]
    float a[VV];
    const float* arow = attn_s + co*700 + lane;   // lane<28 in-bounds via pad
    #pragma unroll
    for (int u = 0; u < VV; u++) a[u] = arow[u*28];

    size_t obase = (((size_t)(n*CO + co0 + co))*TT + tg*32)*VV + lane;
    const float* x3b = x3_s + (tg*32*VV)*8 + co;

    for (int ti = 0; ti < 32; ti++) {
        const float* xr = x3b + ti*VV*8;
        float acc = 0.f;
        #pragma unroll
        for (int u = 0; u < VV; u++)
            acc += a[u] * xr[u*8];        // broadcast LDS
        if (lane < VV)
            out[obase + (size_t)ti*VV] = acc;
    }
}

// ---------------- launch (k_mma in profiled slot 4) ----------------
extern "C" void kernel_launch(void* const* d_in, const int* in_sizes, int n_in,
                              void* d_out, int out_size) {
    const float* x  = (const float*)d_in[0];
    const float* A  = (const float*)d_in[1];
    const float* w1 = (const float*)d_in[2];
    const float* b1 = (const float*)d_in[3];
    const float* w2 = (const float*)d_in[4];
    const float* b2 = (const float*)d_in[5];
    const float* w3 = (const float*)d_in[6];
    const float* b3 = (const float*)d_in[7];
    const float* w4 = (const float*)d_in[8];
    const float* b4 = (const float*)d_in[9];
    float* out = (float*)d_out;

    cudaFuncSetAttribute(k_mma, cudaFuncAttributeMaxDynamicSharedMemorySize, MMA_SMEM);

    k_w3cvt<<<64, 1024>>>(w3);                    // 1
    k_xm   <<<dim3(64, 64), 256>>>(x);            // 2
    k_x12  <<<64, 256>>>(w1, b1, w2, b2);         // 3
    k_mma  <<<dim3(13, 64), 512, MMA_SMEM>>>(x, b3); // 4  <-- profiled
    k_aff  <<<64, 256>>>();                       // 5
    k_attn <<<dim3(10, 4, 64), 256>>>(w4, b4, A); // 6
    k_out  <<<dim3(32, 64), 512>>>(out);          // 7
}